// round 4
// baseline (speedup 1.0000x reference)
#include <cuda_runtime.h>
#include <cuda_bf16.h>
#include <math.h>
#include <cstdint>

// Problem: B=2, T=2048, C=768, H=12, D=64.  M = B*T = 4096 rows.
#define M_ROWS 4096
#define C_DIM  768
#define T_SEQ  2048
#define H_HEADS 12
#define D_HEAD 64
#define QKV_LD (3*C_DIM)   // 2304
#define FC_DIM (4*C_DIM)   // 3072

// ---------------- scratch (device globals: no allocation allowed) -------------
// xn, y, h hold tf32-rounded, k-permuted data (GEMM A operands only)
__device__ float g_xn [M_ROWS * C_DIM];
__device__ float g_qkv[M_ROWS * QKV_LD];
__device__ float g_y  [M_ROWS * C_DIM];
__device__ float g_x2 [M_ROWS * C_DIM];
__device__ float g_h  [M_ROWS * FC_DIM];
// transposed (K-major, tf32-rounded, k-permuted) weights
__device__ float g_wattnT[QKV_LD * C_DIM];
__device__ float g_wprojT[C_DIM * C_DIM];
__device__ float g_wfcT  [FC_DIM * C_DIM];
__device__ float g_wmlpT [C_DIM * FC_DIM];

// ======================= helpers ==============================================
__device__ __forceinline__ uint32_t smem_u32(const void* p) {
    uint32_t a;
    asm("{ .reg .u64 t; cvta.to.shared.u64 t, %1; cvt.u32.u64 %0, t; }" : "=r"(a) : "l"(p));
    return a;
}
__device__ __forceinline__ void cp_async16(uint32_t s, const void* g) {
    asm volatile("cp.async.cg.shared.global [%0], [%1], 16;" :: "r"(s), "l"(g));
}
#define CP_COMMIT() asm volatile("cp.async.commit_group;" ::: "memory")
#define CP_WAIT(n)  asm volatile("cp.async.wait_group %0;" :: "n"(n) : "memory")

__device__ __forceinline__ uint32_t to_tf32(float v) {
    uint32_t r;
    asm("cvt.rna.tf32.f32 %0, %1;" : "=r"(r) : "f"(v));
    return r;
}
__device__ __forceinline__ float tf32f(float v) { return __uint_as_float(to_tf32(v)); }
// permute k within 8-groups so mma fragment pairs (t4, t4+4) are adjacent
__device__ __forceinline__ int permk(int c) {
    return (c & ~7) | ((c & 3) << 1) | ((c >> 2) & 1);
}
// D(16x8) += A(16x8, row) * B(8x8, col) with tf32 inputs, fp32 accum
__device__ __forceinline__ void mma_tf32(float* d, const uint32_t* a, const uint32_t* b) {
    asm volatile(
        "mma.sync.aligned.m16n8k8.row.col.f32.tf32.tf32.f32 "
        "{%0,%1,%2,%3}, {%4,%5,%6,%7}, {%8,%9}, {%0,%1,%2,%3};"
        : "+f"(d[0]), "+f"(d[1]), "+f"(d[2]), "+f"(d[3])
        : "r"(a[0]), "r"(a[1]), "r"(a[2]), "r"(a[3]), "r"(b[0]), "r"(b[1]));
}

// ---------------- LayerNorm (output: tf32-rounded, k-permuted) ----------------
__global__ __launch_bounds__(256) void ln_kernel(const float* __restrict__ x,
                                                 const float* __restrict__ w,
                                                 float* __restrict__ out) {
    int row = blockIdx.x;
    const float* xr = x + (size_t)row * C_DIM;
    float s = 0.f, s2 = 0.f;
    for (int i = threadIdx.x; i < C_DIM; i += 256) {
        float v = xr[i];
        s += v; s2 += v * v;
    }
    #pragma unroll
    for (int o = 16; o; o >>= 1) {
        s  += __shfl_xor_sync(0xFFFFFFFFu, s,  o);
        s2 += __shfl_xor_sync(0xFFFFFFFFu, s2, o);
    }
    __shared__ float ss[8], ss2[8];
    int wid = threadIdx.x >> 5, lid = threadIdx.x & 31;
    if (lid == 0) { ss[wid] = s; ss2[wid] = s2; }
    __syncthreads();
    if (wid == 0) {
        s  = (lid < 8) ? ss[lid]  : 0.f;
        s2 = (lid < 8) ? ss2[lid] : 0.f;
        #pragma unroll
        for (int o = 4; o; o >>= 1) {
            s  += __shfl_xor_sync(0xFFFFFFFFu, s,  o);
            s2 += __shfl_xor_sync(0xFFFFFFFFu, s2, o);
        }
        if (lid == 0) { ss[0] = s; ss2[0] = s2; }
    }
    __syncthreads();
    float mean = ss[0] * (1.f / C_DIM);
    float var  = ss2[0] * (1.f / C_DIM) - mean * mean;
    float inv  = rsqrtf(var + 1e-5f);
    for (int i = threadIdx.x; i < C_DIM; i += 256)
        out[(size_t)row * C_DIM + permk(i)] = tf32f((xr[i] - mean) * inv * w[i]);
}

// ---------------- Weight transpose + tf32 rounding + k-permute ----------------
__global__ __launch_bounds__(256) void transpose_tf32_kernel(const float* __restrict__ in,
                                                             float* __restrict__ out,
                                                             int rows, int cols) {
    __shared__ float tile[32][33];
    int bx = blockIdx.x * 32;
    int by = blockIdx.y * 32;
    int x = bx + threadIdx.x;
    #pragma unroll
    for (int j = 0; j < 32; j += 8)
        tile[threadIdx.y + j][threadIdx.x] = in[(size_t)(by + threadIdx.y + j) * cols + x];
    __syncthreads();
    int ox = by + threadIdx.x;
    #pragma unroll
    for (int j = 0; j < 32; j += 8) {
        float v = tile[threadIdx.x][threadIdx.y + j];
        out[(size_t)(bx + threadIdx.y + j) * rows + permk(ox)] = tf32f(v);
    }
}

// ---------------- mma.sync TF32 GEMM, 128x128 tile, K-chunks of 32 ------------
// A: [M][K] pre-rounded tf32, k-permuted.  BT: [N][K] same.
// MODE 0: C = A@B (fp32 out) ; MODE 1: C = A@B + R (fp32 out) ;
// MODE 2: C = gelu(A@B), tf32-rounded + k-permuted out (feeds next GEMM as A)
#define GSTR 36
#define GBUF (128 * GSTR)                  // floats per operand per stage
#define GEMM_SMEM_BYTES (4 * GBUF * 4)     // 2 stages x (A+B) = 73728

template<int MODE>
__global__ __launch_bounds__(256, 2) void mma_gemm_kernel(
    const float* __restrict__ A, const float* __restrict__ BT,
    const float* __restrict__ R, float* __restrict__ C,
    int M, int N, int K)
{
    extern __shared__ float smf[];
    uint32_t sm_u = smem_u32(smf);

    int tid  = threadIdx.x;
    int wid  = tid >> 5, lane = tid & 31;
    int wm   = wid & 1;          // 0..1 : 64-row slab
    int wn   = wid >> 1;         // 0..3 : 32-col slab
    int g    = lane >> 2, t4 = lane & 3;
    int m0 = blockIdx.y * 128, n0 = blockIdx.x * 128;

    int lrow = tid >> 3;         // 0..31 within a 32-row group
    int lc4  = (tid & 7) * 4;    // 0..28

    float acc[4][4][4];
    #pragma unroll
    for (int i = 0; i < 4; i++)
        #pragma unroll
        for (int j = 0; j < 4; j++)
            #pragma unroll
            for (int q = 0; q < 4; q++) acc[i][j][q] = 0.f;

    const int nch = K >> 5;

    // issue one chunk's cp.async into stage b
    auto issue = [&](int k0, int b) {
        uint32_t aoff = sm_u + (uint32_t)(b * 2 * GBUF) * 4;
        uint32_t boff = aoff + (uint32_t)GBUF * 4;
        #pragma unroll
        for (int t = 0; t < 4; t++) {
            int row = t * 32 + lrow;
            uint32_t so = (uint32_t)((row * GSTR + lc4) * 4);
            cp_async16(aoff + so, A  + (size_t)(m0 + row) * K + k0 + lc4);
            cp_async16(boff + so, BT + (size_t)(n0 + row) * K + k0 + lc4);
        }
    };

    issue(0, 0);
    CP_COMMIT();

    int buf = 0;
    for (int ic = 0; ic < nch; ic++) {
        if (ic + 1 < nch) {
            issue((ic + 1) * 32, buf ^ 1);
            CP_COMMIT();
            CP_WAIT(1);
        } else {
            CP_WAIT(0);
        }
        __syncthreads();

        const float* Af = smf + buf * 2 * GBUF;
        const float* Bf = Af + GBUF;
        #pragma unroll
        for (int ks = 0; ks < 4; ks++) {
            uint32_t a[4][4], b[4][2];
            int kc = ks * 8 + 2 * t4;
            #pragma unroll
            for (int mt = 0; mt < 4; mt++) {
                int r = wm * 64 + mt * 16 + g;
                float2 lo = *(const float2*)(Af + r * GSTR + kc);        // a0,a2
                float2 hi = *(const float2*)(Af + (r + 8) * GSTR + kc);  // a1,a3
                a[mt][0] = __float_as_uint(lo.x); a[mt][2] = __float_as_uint(lo.y);
                a[mt][1] = __float_as_uint(hi.x); a[mt][3] = __float_as_uint(hi.y);
            }
            #pragma unroll
            for (int nt = 0; nt < 4; nt++) {
                int nr = wn * 32 + nt * 8 + g;
                float2 bv = *(const float2*)(Bf + nr * GSTR + kc);       // b0,b1
                b[nt][0] = __float_as_uint(bv.x); b[nt][1] = __float_as_uint(bv.y);
            }
            #pragma unroll
            for (int mt = 0; mt < 4; mt++)
                #pragma unroll
                for (int nt = 0; nt < 4; nt++)
                    mma_tf32(acc[mt][nt], a[mt], b[nt]);
        }
        __syncthreads();
        buf ^= 1;
    }

    // ---- epilogue ----
    #pragma unroll
    for (int mt = 0; mt < 4; mt++) {
        int r0 = m0 + wm * 64 + mt * 16 + g;
        #pragma unroll
        for (int nt = 0; nt < 4; nt++) {
            int c = n0 + wn * 32 + nt * 8 + 2 * t4;
            #pragma unroll
            for (int half = 0; half < 2; half++) {
                int r = r0 + half * 8;
                float v0 = acc[mt][nt][half * 2 + 0];
                float v1 = acc[mt][nt][half * 2 + 1];
                if (MODE == 1) {
                    float2 rv = *(const float2*)(R + (size_t)r * N + c);
                    v0 += rv.x; v1 += rv.y;
                    *(float2*)(C + (size_t)r * N + c) = make_float2(v0, v1);
                } else if (MODE == 2) {
                    v0 = 0.5f * v0 * (1.0f + erff(v0 * 0.70710678118654752f));
                    v1 = 0.5f * v1 * (1.0f + erff(v1 * 0.70710678118654752f));
                    C[(size_t)r * N + permk(c)]     = tf32f(v0);
                    C[(size_t)r * N + permk(c + 1)] = tf32f(v1);
                } else {
                    *(float2*)(C + (size_t)r * N + c) = make_float2(v0, v1);
                }
            }
        }
    }
}

// ---------------- Attention: exp(-sq_l2/(2 sqrt(D))), causal, unnormalized ----
// output y: tf32-rounded + k-permuted (GEMM A operand)
#define AT_STRIDE 68

__global__ __launch_bounds__(256) void attn_kernel(const float* __restrict__ qkv,
                                                   float* __restrict__ y) {
    int qt = blockIdx.x;
    int h  = blockIdx.y;
    int b  = blockIdx.z;

    extern __shared__ float sm[];
    float* Qs = sm;
    float* Ks = Qs + 64 * AT_STRIDE;
    float* Vs = Ks + 64 * AT_STRIDE;
    float* Ss = Vs + 64 * AT_STRIDE;
    float* q2 = Ss + 64 * AT_STRIDE;
    float* k2 = q2 + 64;

    int tid = threadIdx.x;
    int tx = tid & 15, ty = tid >> 4;
    const float scale = -0.0625f;

    const float* qbase = qkv + ((size_t)(b * T_SEQ + qt * 64)) * QKV_LD + h * 64;
    for (int i = tid; i < 64 * 16; i += 256) {
        int row = i >> 4;
        int c4  = (i & 15) * 4;
        *(float4*)(Qs + row * AT_STRIDE + c4) =
            *(const float4*)(qbase + (size_t)row * QKV_LD + c4);
    }
    __syncthreads();
    if (tid < 64) {
        float s = 0.f;
        #pragma unroll 8
        for (int d = 0; d < 64; d++) { float v = Qs[tid * AT_STRIDE + d]; s += v * v; }
        q2[tid] = s;
    }

    float acc[4][4];
    #pragma unroll
    for (int i = 0; i < 4; i++)
        #pragma unroll
        for (int j = 0; j < 4; j++) acc[i][j] = 0.f;

    for (int kt = 0; kt <= qt; kt++) {
        __syncthreads();
        const float* kbase = qkv + ((size_t)(b * T_SEQ + kt * 64)) * QKV_LD + C_DIM + h * 64;
        const float* vbase = kbase + C_DIM;
        for (int i = tid; i < 64 * 16; i += 256) {
            int row = i >> 4;
            int c4  = (i & 15) * 4;
            *(float4*)(Ks + row * AT_STRIDE + c4) =
                *(const float4*)(kbase + (size_t)row * QKV_LD + c4);
            *(float4*)(Vs + row * AT_STRIDE + c4) =
                *(const float4*)(vbase + (size_t)row * QKV_LD + c4);
        }
        __syncthreads();
        if (tid < 64) {
            float s = 0.f;
            #pragma unroll 8
            for (int d = 0; d < 64; d++) { float v = Ks[tid * AT_STRIDE + d]; s += v * v; }
            k2[tid] = s;
        }
        __syncthreads();

        float s_[4][4];
        #pragma unroll
        for (int i = 0; i < 4; i++)
            #pragma unroll
            for (int j = 0; j < 4; j++) s_[i][j] = 0.f;

        #pragma unroll 4
        for (int d4 = 0; d4 < 64; d4 += 4) {
            float4 qv[4], kv[4];
            #pragma unroll
            for (int i = 0; i < 4; i++)
                qv[i] = *(const float4*)(Qs + (ty * 4 + i) * AT_STRIDE + d4);
            #pragma unroll
            for (int j = 0; j < 4; j++)
                kv[j] = *(const float4*)(Ks + (tx * 4 + j) * AT_STRIDE + d4);
            #pragma unroll
            for (int i = 0; i < 4; i++)
                #pragma unroll
                for (int j = 0; j < 4; j++)
                    s_[i][j] += qv[i].x * kv[j].x + qv[i].y * kv[j].y
                              + qv[i].z * kv[j].z + qv[i].w * kv[j].w;
        }

        #pragma unroll
        for (int i = 0; i < 4; i++) {
            int r = ty * 4 + i;
            int qq = qt * 64 + r;
            float q2v = q2[r];
            float4 ov;
            float* o = &ov.x;
            #pragma unroll
            for (int j = 0; j < 4; j++) {
                int cc = tx * 4 + j;
                int kk = kt * 64 + cc;
                float val = __expf(scale * (q2v + k2[cc] - 2.f * s_[i][j]));
                o[j] = (kk <= qq) ? val : 0.f;
            }
            *(float4*)(Ss + r * AT_STRIDE + tx * 4) = ov;
        }
        __syncthreads();

        #pragma unroll 4
        for (int c4 = 0; c4 < 64; c4 += 4) {
            float4 sv[4], vv[4];
            #pragma unroll
            for (int i = 0; i < 4; i++)
                sv[i] = *(const float4*)(Ss + (ty * 4 + i) * AT_STRIDE + c4);
            #pragma unroll
            for (int cc = 0; cc < 4; cc++)
                vv[cc] = *(const float4*)(Vs + (c4 + cc) * AT_STRIDE + tx * 4);
            #pragma unroll
            for (int i = 0; i < 4; i++) {
                acc[i][0] += sv[i].x * vv[0].x + sv[i].y * vv[1].x + sv[i].z * vv[2].x + sv[i].w * vv[3].x;
                acc[i][1] += sv[i].x * vv[0].y + sv[i].y * vv[1].y + sv[i].z * vv[2].y + sv[i].w * vv[3].y;
                acc[i][2] += sv[i].x * vv[0].z + sv[i].y * vv[1].z + sv[i].z * vv[2].z + sv[i].w * vv[3].z;
                acc[i][3] += sv[i].x * vv[0].w + sv[i].y * vv[1].w + sv[i].z * vv[2].w + sv[i].w * vv[3].w;
            }
        }
    }

    float* ybase = y + ((size_t)(b * T_SEQ + qt * 64)) * C_DIM;
    int colbase = h * 64 + tx * 4;
    #pragma unroll
    for (int i = 0; i < 4; i++) {
        float* yr = ybase + (size_t)(ty * 4 + i) * C_DIM;
        #pragma unroll
        for (int j = 0; j < 4; j++)
            yr[permk(colbase + j)] = tf32f(acc[i][j]);
    }
}

// ---------------- launch ------------------------------------------------------
extern "C" void kernel_launch(void* const* d_in, const int* in_sizes, int n_in,
                              void* d_out, int out_size) {
    const float* x           = (const float*)d_in[0];
    const float* w_ln1       = (const float*)d_in[1];
    const float* w_attn      = (const float*)d_in[2];
    const float* w_attn_proj = (const float*)d_in[3];
    const float* w_ln2       = (const float*)d_in[4];
    const float* w_fc        = (const float*)d_in[5];
    const float* w_mlp_proj  = (const float*)d_in[6];
    float* out = (float*)d_out;

    float *xn, *qkv, *y, *x2, *hbuf, *wattnT, *wprojT, *wfcT, *wmlpT;
    cudaGetSymbolAddress((void**)&xn,     g_xn);
    cudaGetSymbolAddress((void**)&qkv,    g_qkv);
    cudaGetSymbolAddress((void**)&y,      g_y);
    cudaGetSymbolAddress((void**)&x2,     g_x2);
    cudaGetSymbolAddress((void**)&hbuf,   g_h);
    cudaGetSymbolAddress((void**)&wattnT, g_wattnT);
    cudaGetSymbolAddress((void**)&wprojT, g_wprojT);
    cudaGetSymbolAddress((void**)&wfcT,   g_wfcT);
    cudaGetSymbolAddress((void**)&wmlpT,  g_wmlpT);

    const int ATTN_SMEM = (4 * 64 * AT_STRIDE + 128) * sizeof(float);
    cudaFuncSetAttribute(attn_kernel, cudaFuncAttributeMaxDynamicSharedMemorySize, ATTN_SMEM);
    cudaFuncSetAttribute(mma_gemm_kernel<0>, cudaFuncAttributeMaxDynamicSharedMemorySize, GEMM_SMEM_BYTES);
    cudaFuncSetAttribute(mma_gemm_kernel<1>, cudaFuncAttributeMaxDynamicSharedMemorySize, GEMM_SMEM_BYTES);
    cudaFuncSetAttribute(mma_gemm_kernel<2>, cudaFuncAttributeMaxDynamicSharedMemorySize, GEMM_SMEM_BYTES);

    dim3 tb(32, 8);
    transpose_tf32_kernel<<<dim3(QKV_LD / 32, C_DIM / 32), tb>>>(w_attn,      wattnT, C_DIM,  QKV_LD);
    transpose_tf32_kernel<<<dim3(C_DIM / 32,  C_DIM / 32), tb>>>(w_attn_proj, wprojT, C_DIM,  C_DIM);
    transpose_tf32_kernel<<<dim3(FC_DIM / 32, C_DIM / 32), tb>>>(w_fc,        wfcT,   C_DIM,  FC_DIM);
    transpose_tf32_kernel<<<dim3(C_DIM / 32,  FC_DIM / 32), tb>>>(w_mlp_proj, wmlpT,  FC_DIM, C_DIM);

    // 1. ln1(x) -> xn  (tf32, k-permuted)
    ln_kernel<<<M_ROWS, 256>>>(x, w_ln1, xn);
    // 2. qkv = xn @ w_attn
    mma_gemm_kernel<0><<<dim3(QKV_LD / 128, M_ROWS / 128), 256, GEMM_SMEM_BYTES>>>(
        xn, wattnT, nullptr, qkv, M_ROWS, QKV_LD, C_DIM);
    // 3. attention -> y (tf32, k-permuted)
    attn_kernel<<<dim3(T_SEQ / 64, H_HEADS, 2), 256, ATTN_SMEM>>>(qkv, y);
    // 4. x2 = y @ w_attn_proj + x
    mma_gemm_kernel<1><<<dim3(C_DIM / 128, M_ROWS / 128), 256, GEMM_SMEM_BYTES>>>(
        y, wprojT, x, x2, M_ROWS, C_DIM, C_DIM);
    // 5. ln2(x2) -> xn
    ln_kernel<<<M_ROWS, 256>>>(x2, w_ln2, xn);
    // 6. h = gelu(xn @ w_fc)  (tf32, k-permuted)
    mma_gemm_kernel<2><<<dim3(FC_DIM / 128, M_ROWS / 128), 256, GEMM_SMEM_BYTES>>>(
        xn, wfcT, nullptr, hbuf, M_ROWS, FC_DIM, C_DIM);
    // 7. out = h @ w_mlp_proj + x2
    mma_gemm_kernel<1><<<dim3(C_DIM / 128, M_ROWS / 128), 256, GEMM_SMEM_BYTES>>>(
        hbuf, wmlpT, x2, out, M_ROWS, C_DIM, FC_DIM);
}

// round 5
// speedup vs baseline: 1.1101x; 1.1101x over previous
#include <cuda_runtime.h>
#include <cuda_bf16.h>
#include <math.h>
#include <cstdint>

// Problem: B=2, T=2048, C=768, H=12, D=64.  M = B*T = 4096 rows.
#define M_ROWS 4096
#define C_DIM  768
#define T_SEQ  2048
#define H_HEADS 12
#define D_HEAD 64
#define QKV_LD (3*C_DIM)   // 2304
#define FC_DIM (4*C_DIM)   // 3072

// ---------------- scratch (device globals: no allocation allowed) -------------
// xn, y, h hold tf32-rounded, k-permuted data (GEMM A operands only)
__device__ float g_xn [M_ROWS * C_DIM];
__device__ float g_qkv[M_ROWS * QKV_LD];
__device__ float g_y  [M_ROWS * C_DIM];
__device__ float g_x2 [M_ROWS * C_DIM];
__device__ float g_h  [M_ROWS * FC_DIM];
// transposed (K-major, tf32-rounded, k-permuted) weights
__device__ float g_wattnT[QKV_LD * C_DIM];
__device__ float g_wprojT[C_DIM * C_DIM];
__device__ float g_wfcT  [FC_DIM * C_DIM];
__device__ float g_wmlpT [C_DIM * FC_DIM];

// ======================= helpers ==============================================
__device__ __forceinline__ uint32_t smem_u32(const void* p) {
    uint32_t a;
    asm("{ .reg .u64 t; cvta.to.shared.u64 t, %1; cvt.u32.u64 %0, t; }" : "=r"(a) : "l"(p));
    return a;
}
__device__ __forceinline__ void cp_async16(uint32_t s, const void* g) {
    asm volatile("cp.async.cg.shared.global [%0], [%1], 16;" :: "r"(s), "l"(g));
}
#define CP_COMMIT() asm volatile("cp.async.commit_group;" ::: "memory")
#define CP_WAIT(n)  asm volatile("cp.async.wait_group %0;" :: "n"(n) : "memory")

__device__ __forceinline__ uint32_t to_tf32(float v) {
    uint32_t r;
    asm("cvt.rna.tf32.f32 %0, %1;" : "=r"(r) : "f"(v));
    return r;
}
__device__ __forceinline__ float tf32f(float v) { return __uint_as_float(to_tf32(v)); }
// permute k within 8-groups so mma fragment pairs (t4, t4+4) are adjacent
__device__ __forceinline__ int permk(int c) {
    return (c & ~7) | ((c & 3) << 1) | ((c >> 2) & 1);
}
// smem swizzle: tile row r, float col k (k even / 16B-aligned accesses only)
__device__ __forceinline__ int swz(int r, int k) {
    return r * 32 + (k ^ ((r & 3) << 3));
}
// D(16x8) += A(16x8, row) * B(8x8, col) with tf32 inputs, fp32 accum
__device__ __forceinline__ void mma_tf32(float* d, const uint32_t* a, const uint32_t* b) {
    asm volatile(
        "mma.sync.aligned.m16n8k8.row.col.f32.tf32.tf32.f32 "
        "{%0,%1,%2,%3}, {%4,%5,%6,%7}, {%8,%9}, {%0,%1,%2,%3};"
        : "+f"(d[0]), "+f"(d[1]), "+f"(d[2]), "+f"(d[3])
        : "r"(a[0]), "r"(a[1]), "r"(a[2]), "r"(a[3]), "r"(b[0]), "r"(b[1]));
}

// ---------------- LayerNorm (output: tf32-rounded, k-permuted) ----------------
__global__ __launch_bounds__(256) void ln_kernel(const float* __restrict__ x,
                                                 const float* __restrict__ w,
                                                 float* __restrict__ out) {
    int row = blockIdx.x;
    const float* xr = x + (size_t)row * C_DIM;
    float s = 0.f, s2 = 0.f;
    for (int i = threadIdx.x; i < C_DIM; i += 256) {
        float v = xr[i];
        s += v; s2 += v * v;
    }
    #pragma unroll
    for (int o = 16; o; o >>= 1) {
        s  += __shfl_xor_sync(0xFFFFFFFFu, s,  o);
        s2 += __shfl_xor_sync(0xFFFFFFFFu, s2, o);
    }
    __shared__ float ss[8], ss2[8];
    int wid = threadIdx.x >> 5, lid = threadIdx.x & 31;
    if (lid == 0) { ss[wid] = s; ss2[wid] = s2; }
    __syncthreads();
    if (wid == 0) {
        s  = (lid < 8) ? ss[lid]  : 0.f;
        s2 = (lid < 8) ? ss2[lid] : 0.f;
        #pragma unroll
        for (int o = 4; o; o >>= 1) {
            s  += __shfl_xor_sync(0xFFFFFFFFu, s,  o);
            s2 += __shfl_xor_sync(0xFFFFFFFFu, s2, o);
        }
        if (lid == 0) { ss[0] = s; ss2[0] = s2; }
    }
    __syncthreads();
    float mean = ss[0] * (1.f / C_DIM);
    float var  = ss2[0] * (1.f / C_DIM) - mean * mean;
    float inv  = rsqrtf(var + 1e-5f);
    for (int i = threadIdx.x; i < C_DIM; i += 256)
        out[(size_t)row * C_DIM + permk(i)] = tf32f((xr[i] - mean) * inv * w[i]);
}

// ---------------- Weight transpose + tf32 rounding + k-permute ----------------
__global__ __launch_bounds__(256) void transpose_tf32_kernel(const float* __restrict__ in,
                                                             float* __restrict__ out,
                                                             int rows, int cols) {
    __shared__ float tile[32][33];
    int bx = blockIdx.x * 32;
    int by = blockIdx.y * 32;
    int x = bx + threadIdx.x;
    #pragma unroll
    for (int j = 0; j < 32; j += 8)
        tile[threadIdx.y + j][threadIdx.x] = in[(size_t)(by + threadIdx.y + j) * cols + x];
    __syncthreads();
    int ox = by + threadIdx.x;
    #pragma unroll
    for (int j = 0; j < 32; j += 8) {
        float v = tile[threadIdx.x][threadIdx.y + j];
        out[(size_t)(bx + threadIdx.y + j) * rows + permk(ox)] = tf32f(v);
    }
}

// ---------------- mma.sync TF32 GEMM, 128x256 CTA tile, warp tile 64x64 -------
// A: [M][K] pre-rounded tf32, k-permuted.  BT: [N][K] same.
// MODE 0: C = A@B ; MODE 1: C = A@B + R ;
// MODE 2: C = gelu(A@B), tf32-rounded + k-permuted out
#define STAGE_F 12288                       // (128 + 256) * 32 floats per stage
#define GEMM_SMEM_BYTES (3 * STAGE_F * 4)   // 147456

template<int MODE>
__global__ __launch_bounds__(256, 1) void mma_gemm_kernel(
    const float* __restrict__ A, const float* __restrict__ BT,
    const float* __restrict__ R, float* __restrict__ C,
    int M, int N, int K)
{
    extern __shared__ float smf[];
    uint32_t sm_u = smem_u32(smf);

    int tid  = threadIdx.x;
    int wid  = tid >> 5, lane = tid & 31;
    int wm   = wid & 1;          // 0..1 : 64-row slab
    int wn   = wid >> 1;         // 0..3 : 64-col slab
    int g    = lane >> 2, t4 = lane & 3;
    int m0 = blockIdx.y * 128, n0 = blockIdx.x * 256;

    int lrow = tid >> 3;         // 0..31
    int lc16 = (tid & 7) * 4;    // 0..28, 16B column within 32-float row

    float acc[4][8][4];
    #pragma unroll
    for (int i = 0; i < 4; i++)
        #pragma unroll
        for (int j = 0; j < 8; j++)
            #pragma unroll
            for (int q = 0; q < 4; q++) acc[i][j][q] = 0.f;

    const int nch = K >> 5;

    // issue one K-chunk's cp.async into stage s
    auto issue = [&](int k0, int s) {
        uint32_t sb = sm_u + (uint32_t)(s * STAGE_F) * 4;
        #pragma unroll
        for (int t = 0; t < 4; t++) {       // A: 128 rows
            int row = t * 32 + lrow;
            cp_async16(sb + (uint32_t)swz(row, lc16) * 4,
                       A + (size_t)(m0 + row) * K + k0 + lc16);
        }
        uint32_t bb = sb + 4096u * 4;       // B: 256 rows
        #pragma unroll
        for (int t = 0; t < 8; t++) {
            int row = t * 32 + lrow;
            cp_async16(bb + (uint32_t)swz(row, lc16) * 4,
                       BT + (size_t)(n0 + row) * K + k0 + lc16);
        }
    };

    issue(0, 0); CP_COMMIT();
    if (nch > 1) { issue(32, 1); CP_COMMIT(); }

    for (int ic = 0; ic < nch; ic++) {
        if (ic + 2 < nch) { issue((ic + 2) * 32, (ic + 2) % 3); CP_COMMIT(); }
        int pend = nch - 1 - ic;
        if (pend >= 2)      CP_WAIT(2);
        else if (pend == 1) CP_WAIT(1);
        else                CP_WAIT(0);
        __syncthreads();

        const float* Af = smf + (ic % 3) * STAGE_F;
        const float* Bf = Af + 4096;
        #pragma unroll
        for (int ks = 0; ks < 4; ks++) {
            uint32_t a[4][4], b[8][2];
            int kc = ks * 8 + 2 * t4;
            #pragma unroll
            for (int mt = 0; mt < 4; mt++) {
                int r = wm * 64 + mt * 16 + g;
                float2 lo = *(const float2*)(Af + swz(r,     kc));   // a0,a2
                float2 hi = *(const float2*)(Af + swz(r + 8, kc));   // a1,a3
                a[mt][0] = __float_as_uint(lo.x); a[mt][2] = __float_as_uint(lo.y);
                a[mt][1] = __float_as_uint(hi.x); a[mt][3] = __float_as_uint(hi.y);
            }
            #pragma unroll
            for (int nt = 0; nt < 8; nt++) {
                int nr = wn * 64 + nt * 8 + g;
                float2 bv = *(const float2*)(Bf + swz(nr, kc));      // b0,b1
                b[nt][0] = __float_as_uint(bv.x); b[nt][1] = __float_as_uint(bv.y);
            }
            #pragma unroll
            for (int mt = 0; mt < 4; mt++)
                #pragma unroll
                for (int nt = 0; nt < 8; nt++)
                    mma_tf32(acc[mt][nt], a[mt], b[nt]);
        }
        __syncthreads();
    }

    // ---- epilogue ----
    #pragma unroll
    for (int mt = 0; mt < 4; mt++) {
        int r0 = m0 + wm * 64 + mt * 16 + g;
        #pragma unroll
        for (int nt = 0; nt < 8; nt++) {
            int c = n0 + wn * 64 + nt * 8 + 2 * t4;
            #pragma unroll
            for (int half = 0; half < 2; half++) {
                int r = r0 + half * 8;
                float v0 = acc[mt][nt][half * 2 + 0];
                float v1 = acc[mt][nt][half * 2 + 1];
                if (MODE == 1) {
                    float2 rv = *(const float2*)(R + (size_t)r * N + c);
                    v0 += rv.x; v1 += rv.y;
                    *(float2*)(C + (size_t)r * N + c) = make_float2(v0, v1);
                } else if (MODE == 2) {
                    v0 = 0.5f * v0 * (1.0f + erff(v0 * 0.70710678118654752f));
                    v1 = 0.5f * v1 * (1.0f + erff(v1 * 0.70710678118654752f));
                    C[(size_t)r * N + permk(c)]     = tf32f(v0);
                    C[(size_t)r * N + permk(c + 1)] = tf32f(v1);
                } else {
                    *(float2*)(C + (size_t)r * N + c) = make_float2(v0, v1);
                }
            }
        }
    }
}

// ---------------- Attention: exp(-sq_l2/(2 sqrt(D))), causal, unnormalized ----
// output y: tf32-rounded + k-permuted (GEMM A operand)
#define AT_STRIDE 68

__global__ __launch_bounds__(256) void attn_kernel(const float* __restrict__ qkv,
                                                   float* __restrict__ y) {
    int qt = blockIdx.x;
    int h  = blockIdx.y;
    int b  = blockIdx.z;

    extern __shared__ float sm[];
    float* Qs = sm;
    float* Ks = Qs + 64 * AT_STRIDE;
    float* Vs = Ks + 64 * AT_STRIDE;
    float* Ss = Vs + 64 * AT_STRIDE;
    float* q2 = Ss + 64 * AT_STRIDE;
    float* k2 = q2 + 64;

    int tid = threadIdx.x;
    int tx = tid & 15, ty = tid >> 4;
    const float scale = -0.0625f;

    const float* qbase = qkv + ((size_t)(b * T_SEQ + qt * 64)) * QKV_LD + h * 64;
    for (int i = tid; i < 64 * 16; i += 256) {
        int row = i >> 4;
        int c4  = (i & 15) * 4;
        *(float4*)(Qs + row * AT_STRIDE + c4) =
            *(const float4*)(qbase + (size_t)row * QKV_LD + c4);
    }
    __syncthreads();
    if (tid < 64) {
        float s = 0.f;
        #pragma unroll 8
        for (int d = 0; d < 64; d++) { float v = Qs[tid * AT_STRIDE + d]; s += v * v; }
        q2[tid] = s;
    }

    float acc[4][4];
    #pragma unroll
    for (int i = 0; i < 4; i++)
        #pragma unroll
        for (int j = 0; j < 4; j++) acc[i][j] = 0.f;

    for (int kt = 0; kt <= qt; kt++) {
        __syncthreads();
        const float* kbase = qkv + ((size_t)(b * T_SEQ + kt * 64)) * QKV_LD + C_DIM + h * 64;
        const float* vbase = kbase + C_DIM;
        for (int i = tid; i < 64 * 16; i += 256) {
            int row = i >> 4;
            int c4  = (i & 15) * 4;
            *(float4*)(Ks + row * AT_STRIDE + c4) =
                *(const float4*)(kbase + (size_t)row * QKV_LD + c4);
            *(float4*)(Vs + row * AT_STRIDE + c4) =
                *(const float4*)(vbase + (size_t)row * QKV_LD + c4);
        }
        __syncthreads();
        if (tid < 64) {
            float s = 0.f;
            #pragma unroll 8
            for (int d = 0; d < 64; d++) { float v = Ks[tid * AT_STRIDE + d]; s += v * v; }
            k2[tid] = s;
        }
        __syncthreads();

        float s_[4][4];
        #pragma unroll
        for (int i = 0; i < 4; i++)
            #pragma unroll
            for (int j = 0; j < 4; j++) s_[i][j] = 0.f;

        #pragma unroll 4
        for (int d4 = 0; d4 < 64; d4 += 4) {
            float4 qv[4], kv[4];
            #pragma unroll
            for (int i = 0; i < 4; i++)
                qv[i] = *(const float4*)(Qs + (ty * 4 + i) * AT_STRIDE + d4);
            #pragma unroll
            for (int j = 0; j < 4; j++)
                kv[j] = *(const float4*)(Ks + (tx * 4 + j) * AT_STRIDE + d4);
            #pragma unroll
            for (int i = 0; i < 4; i++)
                #pragma unroll
                for (int j = 0; j < 4; j++)
                    s_[i][j] += qv[i].x * kv[j].x + qv[i].y * kv[j].y
                              + qv[i].z * kv[j].z + qv[i].w * kv[j].w;
        }

        #pragma unroll
        for (int i = 0; i < 4; i++) {
            int r = ty * 4 + i;
            int qq = qt * 64 + r;
            float q2v = q2[r];
            float4 ov;
            float* o = &ov.x;
            #pragma unroll
            for (int j = 0; j < 4; j++) {
                int cc = tx * 4 + j;
                int kk = kt * 64 + cc;
                float val = __expf(scale * (q2v + k2[cc] - 2.f * s_[i][j]));
                o[j] = (kk <= qq) ? val : 0.f;
            }
            *(float4*)(Ss + r * AT_STRIDE + tx * 4) = ov;
        }
        __syncthreads();

        #pragma unroll 4
        for (int c4 = 0; c4 < 64; c4 += 4) {
            float4 sv[4], vv[4];
            #pragma unroll
            for (int i = 0; i < 4; i++)
                sv[i] = *(const float4*)(Ss + (ty * 4 + i) * AT_STRIDE + c4);
            #pragma unroll
            for (int cc = 0; cc < 4; cc++)
                vv[cc] = *(const float4*)(Vs + (c4 + cc) * AT_STRIDE + tx * 4);
            #pragma unroll
            for (int i = 0; i < 4; i++) {
                acc[i][0] += sv[i].x * vv[0].x + sv[i].y * vv[1].x + sv[i].z * vv[2].x + sv[i].w * vv[3].x;
                acc[i][1] += sv[i].x * vv[0].y + sv[i].y * vv[1].y + sv[i].z * vv[2].y + sv[i].w * vv[3].y;
                acc[i][2] += sv[i].x * vv[0].z + sv[i].y * vv[1].z + sv[i].z * vv[2].z + sv[i].w * vv[3].z;
                acc[i][3] += sv[i].x * vv[0].w + sv[i].y * vv[1].w + sv[i].z * vv[2].w + sv[i].w * vv[3].w;
            }
        }
    }

    float* ybase = y + ((size_t)(b * T_SEQ + qt * 64)) * C_DIM;
    int colbase = h * 64 + tx * 4;
    #pragma unroll
    for (int i = 0; i < 4; i++) {
        float* yr = ybase + (size_t)(ty * 4 + i) * C_DIM;
        #pragma unroll
        for (int j = 0; j < 4; j++)
            yr[permk(colbase + j)] = tf32f(acc[i][j]);
    }
}

// ---------------- launch ------------------------------------------------------
extern "C" void kernel_launch(void* const* d_in, const int* in_sizes, int n_in,
                              void* d_out, int out_size) {
    const float* x           = (const float*)d_in[0];
    const float* w_ln1       = (const float*)d_in[1];
    const float* w_attn      = (const float*)d_in[2];
    const float* w_attn_proj = (const float*)d_in[3];
    const float* w_ln2       = (const float*)d_in[4];
    const float* w_fc        = (const float*)d_in[5];
    const float* w_mlp_proj  = (const float*)d_in[6];
    float* out = (float*)d_out;

    float *xn, *qkv, *y, *x2, *hbuf, *wattnT, *wprojT, *wfcT, *wmlpT;
    cudaGetSymbolAddress((void**)&xn,     g_xn);
    cudaGetSymbolAddress((void**)&qkv,    g_qkv);
    cudaGetSymbolAddress((void**)&y,      g_y);
    cudaGetSymbolAddress((void**)&x2,     g_x2);
    cudaGetSymbolAddress((void**)&hbuf,   g_h);
    cudaGetSymbolAddress((void**)&wattnT, g_wattnT);
    cudaGetSymbolAddress((void**)&wprojT, g_wprojT);
    cudaGetSymbolAddress((void**)&wfcT,   g_wfcT);
    cudaGetSymbolAddress((void**)&wmlpT,  g_wmlpT);

    const int ATTN_SMEM = (4 * 64 * AT_STRIDE + 128) * sizeof(float);
    cudaFuncSetAttribute(attn_kernel, cudaFuncAttributeMaxDynamicSharedMemorySize, ATTN_SMEM);
    cudaFuncSetAttribute(mma_gemm_kernel<0>, cudaFuncAttributeMaxDynamicSharedMemorySize, GEMM_SMEM_BYTES);
    cudaFuncSetAttribute(mma_gemm_kernel<1>, cudaFuncAttributeMaxDynamicSharedMemorySize, GEMM_SMEM_BYTES);
    cudaFuncSetAttribute(mma_gemm_kernel<2>, cudaFuncAttributeMaxDynamicSharedMemorySize, GEMM_SMEM_BYTES);

    dim3 tb(32, 8);
    transpose_tf32_kernel<<<dim3(QKV_LD / 32, C_DIM / 32), tb>>>(w_attn,      wattnT, C_DIM,  QKV_LD);
    transpose_tf32_kernel<<<dim3(C_DIM / 32,  C_DIM / 32), tb>>>(w_attn_proj, wprojT, C_DIM,  C_DIM);
    transpose_tf32_kernel<<<dim3(FC_DIM / 32, C_DIM / 32), tb>>>(w_fc,        wfcT,   C_DIM,  FC_DIM);
    transpose_tf32_kernel<<<dim3(C_DIM / 32,  FC_DIM / 32), tb>>>(w_mlp_proj, wmlpT,  FC_DIM, C_DIM);

    // 1. ln1(x) -> xn  (tf32, k-permuted)
    ln_kernel<<<M_ROWS, 256>>>(x, w_ln1, xn);
    // 2. qkv = xn @ w_attn
    mma_gemm_kernel<0><<<dim3(QKV_LD / 256, M_ROWS / 128), 256, GEMM_SMEM_BYTES>>>(
        xn, wattnT, nullptr, qkv, M_ROWS, QKV_LD, C_DIM);
    // 3. attention -> y (tf32, k-permuted)
    attn_kernel<<<dim3(T_SEQ / 64, H_HEADS, 2), 256, ATTN_SMEM>>>(qkv, y);
    // 4. x2 = y @ w_attn_proj + x
    mma_gemm_kernel<1><<<dim3(C_DIM / 256, M_ROWS / 128), 256, GEMM_SMEM_BYTES>>>(
        y, wprojT, x, x2, M_ROWS, C_DIM, C_DIM);
    // 5. ln2(x2) -> xn
    ln_kernel<<<M_ROWS, 256>>>(x2, w_ln2, xn);
    // 6. h = gelu(xn @ w_fc)  (tf32, k-permuted)
    mma_gemm_kernel<2><<<dim3(FC_DIM / 256, M_ROWS / 128), 256, GEMM_SMEM_BYTES>>>(
        xn, wfcT, nullptr, hbuf, M_ROWS, FC_DIM, C_DIM);
    // 7. out = h @ w_mlp_proj + x2
    mma_gemm_kernel<1><<<dim3(C_DIM / 256, M_ROWS / 128), 256, GEMM_SMEM_BYTES>>>(
        hbuf, wmlpT, x2, out, M_ROWS, C_DIM, FC_DIM);
}

// round 6
// speedup vs baseline: 1.2424x; 1.1192x over previous
#include <cuda_runtime.h>
#include <cuda_fp16.h>
#include <math.h>
#include <cstdint>

// Problem: B=2, T=2048, C=768, H=12, D=64.  M = B*T = 4096 rows.
#define M_ROWS 4096
#define C_DIM  768
#define T_SEQ  2048
#define H_HEADS 12
#define D_HEAD 64
#define QKV_LD (3*C_DIM)   // 2304
#define FC_DIM (4*C_DIM)   // 3072

// ---------------- scratch (device globals: no allocation allowed) -------------
// xn, y, h hold fp16, k-permuted data (GEMM A operands only)
__device__ __half g_xn [M_ROWS * C_DIM];
__device__ float  g_qkv[M_ROWS * QKV_LD];
__device__ __half g_y  [M_ROWS * C_DIM];
__device__ float  g_x2 [M_ROWS * C_DIM];
__device__ __half g_h  [M_ROWS * FC_DIM];
// transposed (K-major, fp16, k-permuted) weights
__device__ __half g_wattnT[QKV_LD * C_DIM];
__device__ __half g_wprojT[C_DIM * C_DIM];
__device__ __half g_wfcT  [FC_DIM * C_DIM];
__device__ __half g_wmlpT [C_DIM * FC_DIM];

// ======================= helpers ==============================================
__device__ __forceinline__ uint32_t smem_u32(const void* p) {
    uint32_t a;
    asm("{ .reg .u64 t; cvta.to.shared.u64 t, %1; cvt.u32.u64 %0, t; }" : "=r"(a) : "l"(p));
    return a;
}
__device__ __forceinline__ void cp_async16(uint32_t s, const void* g) {
    asm volatile("cp.async.cg.shared.global [%0], [%1], 16;" :: "r"(s), "l"(g));
}
#define CP_COMMIT() asm volatile("cp.async.commit_group;" ::: "memory")
#define CP_WAIT(n)  asm volatile("cp.async.wait_group %0;" :: "n"(n) : "memory")

// permute k within 16-groups: a thread's mma fragment halves
// {2t4, 2t4+1, 2t4+8, 2t4+9} become 4 contiguous halves at 16g + 4*t4.
__device__ __forceinline__ int perm16(int k) {
    int lo = k & 15;
    int p = ((lo & 7) >> 1) * 4 + ((lo >> 3) << 1) + (lo & 1);
    return (k & ~15) | p;
}
// smem half-index for tile row r, half col k (k multiple of 4); 16B-unit XOR swizzle
__device__ __forceinline__ int haddr(int r, int k) {
    int u = k >> 3;
    return r * 64 + (((u ^ (r & 7)) << 3) | (k & 7));
}
// D(16x8,f32) += A(16x16,f16) * B(16x8,f16)
__device__ __forceinline__ void mma_f16(float* d, const uint32_t* a, const uint32_t* b) {
    asm volatile(
        "mma.sync.aligned.m16n8k16.row.col.f32.f16.f16.f32 "
        "{%0,%1,%2,%3}, {%4,%5,%6,%7}, {%8,%9}, {%0,%1,%2,%3};"
        : "+f"(d[0]), "+f"(d[1]), "+f"(d[2]), "+f"(d[3])
        : "r"(a[0]), "r"(a[1]), "r"(a[2]), "r"(a[3]), "r"(b[0]), "r"(b[1]));
}

// ---------------- LayerNorm (output: fp16, k-permuted) ------------------------
__global__ __launch_bounds__(256) void ln_kernel(const float* __restrict__ x,
                                                 const float* __restrict__ w,
                                                 __half* __restrict__ out) {
    int row = blockIdx.x;
    const float* xr = x + (size_t)row * C_DIM;
    float s = 0.f, s2 = 0.f;
    for (int i = threadIdx.x; i < C_DIM; i += 256) {
        float v = xr[i];
        s += v; s2 += v * v;
    }
    #pragma unroll
    for (int o = 16; o; o >>= 1) {
        s  += __shfl_xor_sync(0xFFFFFFFFu, s,  o);
        s2 += __shfl_xor_sync(0xFFFFFFFFu, s2, o);
    }
    __shared__ float ss[8], ss2[8];
    int wid = threadIdx.x >> 5, lid = threadIdx.x & 31;
    if (lid == 0) { ss[wid] = s; ss2[wid] = s2; }
    __syncthreads();
    if (wid == 0) {
        s  = (lid < 8) ? ss[lid]  : 0.f;
        s2 = (lid < 8) ? ss2[lid] : 0.f;
        #pragma unroll
        for (int o = 4; o; o >>= 1) {
            s  += __shfl_xor_sync(0xFFFFFFFFu, s,  o);
            s2 += __shfl_xor_sync(0xFFFFFFFFu, s2, o);
        }
        if (lid == 0) { ss[0] = s; ss2[0] = s2; }
    }
    __syncthreads();
    float mean = ss[0] * (1.f / C_DIM);
    float var  = ss2[0] * (1.f / C_DIM) - mean * mean;
    float inv  = rsqrtf(var + 1e-5f);
    for (int i = threadIdx.x; i < C_DIM; i += 256)
        out[(size_t)row * C_DIM + perm16(i)] = __float2half((xr[i] - mean) * inv * w[i]);
}

// ---------------- Weight transpose -> fp16, k-permuted ------------------------
__global__ __launch_bounds__(256) void transpose_h_kernel(const float* __restrict__ in,
                                                          __half* __restrict__ out,
                                                          int rows, int cols) {
    __shared__ float tile[32][33];
    int bx = blockIdx.x * 32;
    int by = blockIdx.y * 32;
    int x = bx + threadIdx.x;
    #pragma unroll
    for (int j = 0; j < 32; j += 8)
        tile[threadIdx.y + j][threadIdx.x] = in[(size_t)(by + threadIdx.y + j) * cols + x];
    __syncthreads();
    int ox = by + threadIdx.x;
    #pragma unroll
    for (int j = 0; j < 32; j += 8) {
        float v = tile[threadIdx.x][threadIdx.y + j];
        out[(size_t)(bx + threadIdx.y + j) * rows + perm16(ox)] = __float2half(v);
    }
}

// ---------------- fp16 mma GEMM, 128x256 CTA tile, warp tile 64x64 ------------
// A: [M][K] fp16 k-permuted.  BT: [N][K] fp16 k-permuted.  K chunk = 64.
// MODE 0: C = A@B (f32) ; MODE 1: C = A@B + R (f32) ;
// MODE 2: C = gelu(A@B) -> fp16, k-permuted
#define STAGE_H 24576                        // (128 + 256) * 64 halves
#define GEMM_SMEM_BYTES (3 * STAGE_H * 2)    // 147456

template<int MODE>
__global__ __launch_bounds__(256, 1) void mma_gemm_kernel(
    const __half* __restrict__ A, const __half* __restrict__ BT,
    const float* __restrict__ R, void* __restrict__ Cv,
    int M, int N, int K)
{
    extern __shared__ __half smh[];
    uint32_t sm_u = smem_u32(smh);

    int tid  = threadIdx.x;
    int wid  = tid >> 5, lane = tid & 31;
    int wm   = wid & 1;          // 0..1 : 64-row slab
    int wn   = wid >> 1;         // 0..3 : 64-col slab
    int g    = lane >> 2, t4 = lane & 3;
    int m0 = blockIdx.y * 128, n0 = blockIdx.x * 256;

    float acc[4][8][4];
    #pragma unroll
    for (int i = 0; i < 4; i++)
        #pragma unroll
        for (int j = 0; j < 8; j++)
            #pragma unroll
            for (int q = 0; q < 4; q++) acc[i][j][q] = 0.f;

    const int nch = K >> 6;      // chunks of 64 halves

    auto issue = [&](int k0, int s) {
        uint32_t sb = sm_u + (uint32_t)(s * STAGE_H) * 2;
        #pragma unroll
        for (int t = 0; t < 4; t++) {            // A: 128 rows x 8 units
            int idx = t * 256 + tid;
            int row = idx >> 3, u = idx & 7;
            cp_async16(sb + (uint32_t)(row * 64 + ((u ^ (row & 7)) << 3)) * 2,
                       A + (size_t)(m0 + row) * K + k0 + u * 8);
        }
        uint32_t bb = sb + 8192u * 2;            // B: 256 rows x 8 units
        #pragma unroll
        for (int t = 0; t < 8; t++) {
            int idx = t * 256 + tid;
            int row = idx >> 3, u = idx & 7;
            cp_async16(bb + (uint32_t)(row * 64 + ((u ^ (row & 7)) << 3)) * 2,
                       BT + (size_t)(n0 + row) * K + k0 + u * 8);
        }
    };

    issue(0, 0); CP_COMMIT();
    if (nch > 1) { issue(64, 1); CP_COMMIT(); }

    for (int ic = 0; ic < nch; ic++) {
        if (ic + 2 < nch) { issue((ic + 2) * 64, (ic + 2) % 3); CP_COMMIT(); }
        int pend = nch - 1 - ic;
        if (pend >= 2)      CP_WAIT(2);
        else if (pend == 1) CP_WAIT(1);
        else                CP_WAIT(0);
        __syncthreads();

        const __half* Ah = smh + (ic % 3) * STAGE_H;
        const __half* Bh = Ah + 8192;
        #pragma unroll
        for (int ks = 0; ks < 4; ks++) {         // 4 x K16
            uint32_t a[4][4], b[8][2];
            int kc = ks * 16 + 4 * t4;
            #pragma unroll
            for (int mt = 0; mt < 4; mt++) {
                int r = wm * 64 + mt * 16 + g;
                uint2 lo = *(const uint2*)(Ah + haddr(r,     kc));  // a0,a2
                uint2 hi = *(const uint2*)(Ah + haddr(r + 8, kc));  // a1,a3
                a[mt][0] = lo.x; a[mt][2] = lo.y;
                a[mt][1] = hi.x; a[mt][3] = hi.y;
            }
            #pragma unroll
            for (int nt = 0; nt < 8; nt++) {
                int nr = wn * 64 + nt * 8 + g;
                uint2 bv = *(const uint2*)(Bh + haddr(nr, kc));     // b0,b1
                b[nt][0] = bv.x; b[nt][1] = bv.y;
            }
            #pragma unroll
            for (int mt = 0; mt < 4; mt++)
                #pragma unroll
                for (int nt = 0; nt < 8; nt++)
                    mma_f16(acc[mt][nt], a[mt], b[nt]);
        }
        __syncthreads();
    }

    // ---- epilogue ----
    #pragma unroll
    for (int mt = 0; mt < 4; mt++) {
        int r0 = m0 + wm * 64 + mt * 16 + g;
        #pragma unroll
        for (int nt = 0; nt < 8; nt++) {
            int c = n0 + wn * 64 + nt * 8 + 2 * t4;
            #pragma unroll
            for (int half_ = 0; half_ < 2; half_++) {
                int r = r0 + half_ * 8;
                float v0 = acc[mt][nt][half_ * 2 + 0];
                float v1 = acc[mt][nt][half_ * 2 + 1];
                if (MODE == 1) {
                    float* C = (float*)Cv;
                    float2 rv = *(const float2*)(R + (size_t)r * N + c);
                    v0 += rv.x; v1 += rv.y;
                    *(float2*)(C + (size_t)r * N + c) = make_float2(v0, v1);
                } else if (MODE == 2) {
                    __half* C = (__half*)Cv;
                    v0 = 0.5f * v0 * (1.0f + erff(v0 * 0.70710678118654752f));
                    v1 = 0.5f * v1 * (1.0f + erff(v1 * 0.70710678118654752f));
                    C[(size_t)r * N + perm16(c)]     = __float2half(v0);
                    C[(size_t)r * N + perm16(c + 1)] = __float2half(v1);
                } else {
                    float* C = (float*)Cv;
                    *(float2*)(C + (size_t)r * N + c) = make_float2(v0, v1);
                }
            }
        }
    }
}

// ---------------- Attention: exp(-sq_l2/(2 sqrt(D))), causal, unnormalized ----
// output y: fp16, k-permuted (GEMM A operand)
#define AT_STRIDE 68

__global__ __launch_bounds__(256) void attn_kernel(const float* __restrict__ qkv,
                                                   __half* __restrict__ y) {
    int qt = blockIdx.x;
    int h  = blockIdx.y;
    int b  = blockIdx.z;

    extern __shared__ float sm[];
    float* Qs = sm;
    float* Ks = Qs + 64 * AT_STRIDE;
    float* Vs = Ks + 64 * AT_STRIDE;
    float* Ss = Vs + 64 * AT_STRIDE;
    float* q2 = Ss + 64 * AT_STRIDE;
    float* k2 = q2 + 64;

    int tid = threadIdx.x;
    int tx = tid & 15, ty = tid >> 4;
    const float scale = -0.0625f;

    const float* qbase = qkv + ((size_t)(b * T_SEQ + qt * 64)) * QKV_LD + h * 64;
    for (int i = tid; i < 64 * 16; i += 256) {
        int row = i >> 4;
        int c4  = (i & 15) * 4;
        *(float4*)(Qs + row * AT_STRIDE + c4) =
            *(const float4*)(qbase + (size_t)row * QKV_LD + c4);
    }
    __syncthreads();
    if (tid < 64) {
        float s = 0.f;
        #pragma unroll 8
        for (int d = 0; d < 64; d++) { float v = Qs[tid * AT_STRIDE + d]; s += v * v; }
        q2[tid] = s;
    }

    float acc[4][4];
    #pragma unroll
    for (int i = 0; i < 4; i++)
        #pragma unroll
        for (int j = 0; j < 4; j++) acc[i][j] = 0.f;

    for (int kt = 0; kt <= qt; kt++) {
        __syncthreads();
        const float* kbase = qkv + ((size_t)(b * T_SEQ + kt * 64)) * QKV_LD + C_DIM + h * 64;
        const float* vbase = kbase + C_DIM;
        for (int i = tid; i < 64 * 16; i += 256) {
            int row = i >> 4;
            int c4  = (i & 15) * 4;
            *(float4*)(Ks + row * AT_STRIDE + c4) =
                *(const float4*)(kbase + (size_t)row * QKV_LD + c4);
            *(float4*)(Vs + row * AT_STRIDE + c4) =
                *(const float4*)(vbase + (size_t)row * QKV_LD + c4);
        }
        __syncthreads();
        if (tid < 64) {
            float s = 0.f;
            #pragma unroll 8
            for (int d = 0; d < 64; d++) { float v = Ks[tid * AT_STRIDE + d]; s += v * v; }
            k2[tid] = s;
        }
        __syncthreads();

        float s_[4][4];
        #pragma unroll
        for (int i = 0; i < 4; i++)
            #pragma unroll
            for (int j = 0; j < 4; j++) s_[i][j] = 0.f;

        #pragma unroll 4
        for (int d4 = 0; d4 < 64; d4 += 4) {
            float4 qv[4], kv[4];
            #pragma unroll
            for (int i = 0; i < 4; i++)
                qv[i] = *(const float4*)(Qs + (ty * 4 + i) * AT_STRIDE + d4);
            #pragma unroll
            for (int j = 0; j < 4; j++)
                kv[j] = *(const float4*)(Ks + (tx * 4 + j) * AT_STRIDE + d4);
            #pragma unroll
            for (int i = 0; i < 4; i++)
                #pragma unroll
                for (int j = 0; j < 4; j++)
                    s_[i][j] += qv[i].x * kv[j].x + qv[i].y * kv[j].y
                              + qv[i].z * kv[j].z + qv[i].w * kv[j].w;
        }

        #pragma unroll
        for (int i = 0; i < 4; i++) {
            int r = ty * 4 + i;
            int qq = qt * 64 + r;
            float q2v = q2[r];
            float4 ov;
            float* o = &ov.x;
            #pragma unroll
            for (int j = 0; j < 4; j++) {
                int cc = tx * 4 + j;
                int kk = kt * 64 + cc;
                float val = __expf(scale * (q2v + k2[cc] - 2.f * s_[i][j]));
                o[j] = (kk <= qq) ? val : 0.f;
            }
            *(float4*)(Ss + r * AT_STRIDE + tx * 4) = ov;
        }
        __syncthreads();

        #pragma unroll 4
        for (int c4 = 0; c4 < 64; c4 += 4) {
            float4 sv[4], vv[4];
            #pragma unroll
            for (int i = 0; i < 4; i++)
                sv[i] = *(const float4*)(Ss + (ty * 4 + i) * AT_STRIDE + c4);
            #pragma unroll
            for (int cc = 0; cc < 4; cc++)
                vv[cc] = *(const float4*)(Vs + (c4 + cc) * AT_STRIDE + tx * 4);
            #pragma unroll
            for (int i = 0; i < 4; i++) {
                acc[i][0] += sv[i].x * vv[0].x + sv[i].y * vv[1].x + sv[i].z * vv[2].x + sv[i].w * vv[3].x;
                acc[i][1] += sv[i].x * vv[0].y + sv[i].y * vv[1].y + sv[i].z * vv[2].y + sv[i].w * vv[3].y;
                acc[i][2] += sv[i].x * vv[0].z + sv[i].y * vv[1].z + sv[i].z * vv[2].z + sv[i].w * vv[3].z;
                acc[i][3] += sv[i].x * vv[0].w + sv[i].y * vv[1].w + sv[i].z * vv[2].w + sv[i].w * vv[3].w;
            }
        }
    }

    __half* ybase = y + ((size_t)(b * T_SEQ + qt * 64)) * C_DIM;
    int colbase = h * 64 + tx * 4;
    #pragma unroll
    for (int i = 0; i < 4; i++) {
        __half* yr = ybase + (size_t)(ty * 4 + i) * C_DIM;
        #pragma unroll
        for (int j = 0; j < 4; j++)
            yr[perm16(colbase + j)] = __float2half(acc[i][j]);
    }
}

// ---------------- launch ------------------------------------------------------
extern "C" void kernel_launch(void* const* d_in, const int* in_sizes, int n_in,
                              void* d_out, int out_size) {
    const float* x           = (const float*)d_in[0];
    const float* w_ln1       = (const float*)d_in[1];
    const float* w_attn      = (const float*)d_in[2];
    const float* w_attn_proj = (const float*)d_in[3];
    const float* w_ln2       = (const float*)d_in[4];
    const float* w_fc        = (const float*)d_in[5];
    const float* w_mlp_proj  = (const float*)d_in[6];
    float* out = (float*)d_out;

    __half *xn, *y, *hbuf, *wattnT, *wprojT, *wfcT, *wmlpT;
    float *qkv, *x2;
    cudaGetSymbolAddress((void**)&xn,     g_xn);
    cudaGetSymbolAddress((void**)&qkv,    g_qkv);
    cudaGetSymbolAddress((void**)&y,      g_y);
    cudaGetSymbolAddress((void**)&x2,     g_x2);
    cudaGetSymbolAddress((void**)&hbuf,   g_h);
    cudaGetSymbolAddress((void**)&wattnT, g_wattnT);
    cudaGetSymbolAddress((void**)&wprojT, g_wprojT);
    cudaGetSymbolAddress((void**)&wfcT,   g_wfcT);
    cudaGetSymbolAddress((void**)&wmlpT,  g_wmlpT);

    const int ATTN_SMEM = (4 * 64 * AT_STRIDE + 128) * sizeof(float);
    cudaFuncSetAttribute(attn_kernel, cudaFuncAttributeMaxDynamicSharedMemorySize, ATTN_SMEM);
    cudaFuncSetAttribute(mma_gemm_kernel<0>, cudaFuncAttributeMaxDynamicSharedMemorySize, GEMM_SMEM_BYTES);
    cudaFuncSetAttribute(mma_gemm_kernel<1>, cudaFuncAttributeMaxDynamicSharedMemorySize, GEMM_SMEM_BYTES);
    cudaFuncSetAttribute(mma_gemm_kernel<2>, cudaFuncAttributeMaxDynamicSharedMemorySize, GEMM_SMEM_BYTES);

    dim3 tb(32, 8);
    transpose_h_kernel<<<dim3(QKV_LD / 32, C_DIM / 32), tb>>>(w_attn,      wattnT, C_DIM,  QKV_LD);
    transpose_h_kernel<<<dim3(C_DIM / 32,  C_DIM / 32), tb>>>(w_attn_proj, wprojT, C_DIM,  C_DIM);
    transpose_h_kernel<<<dim3(FC_DIM / 32, C_DIM / 32), tb>>>(w_fc,        wfcT,   C_DIM,  FC_DIM);
    transpose_h_kernel<<<dim3(C_DIM / 32,  FC_DIM / 32), tb>>>(w_mlp_proj, wmlpT,  FC_DIM, C_DIM);

    // 1. ln1(x) -> xn  (fp16, k-permuted)
    ln_kernel<<<M_ROWS, 256>>>(x, w_ln1, xn);
    // 2. qkv = xn @ w_attn  (f32 out)
    mma_gemm_kernel<0><<<dim3(QKV_LD / 256, M_ROWS / 128), 256, GEMM_SMEM_BYTES>>>(
        xn, wattnT, nullptr, qkv, M_ROWS, QKV_LD, C_DIM);
    // 3. attention -> y (fp16, k-permuted)
    attn_kernel<<<dim3(T_SEQ / 64, H_HEADS, 2), 256, ATTN_SMEM>>>(qkv, y);
    // 4. x2 = y @ w_attn_proj + x  (f32 out)
    mma_gemm_kernel<1><<<dim3(C_DIM / 256, M_ROWS / 128), 256, GEMM_SMEM_BYTES>>>(
        y, wprojT, x, x2, M_ROWS, C_DIM, C_DIM);
    // 5. ln2(x2) -> xn
    ln_kernel<<<M_ROWS, 256>>>(x2, w_ln2, xn);
    // 6. h = gelu(xn @ w_fc)  (fp16, k-permuted)
    mma_gemm_kernel<2><<<dim3(FC_DIM / 256, M_ROWS / 128), 256, GEMM_SMEM_BYTES>>>(
        xn, wfcT, nullptr, hbuf, M_ROWS, FC_DIM, C_DIM);
    // 7. out = h @ w_mlp_proj + x2  (f32 out)
    mma_gemm_kernel<1><<<dim3(C_DIM / 256, M_ROWS / 128), 256, GEMM_SMEM_BYTES>>>(
        hbuf, wmlpT, x2, out, M_ROWS, C_DIM, FC_DIM);
}

// round 7
// speedup vs baseline: 3.0921x; 2.4888x over previous
#include <cuda_runtime.h>
#include <cuda_fp16.h>
#include <math.h>
#include <cstdint>

// Problem: B=2, T=2048, C=768, H=12, D=64.  M = B*T = 4096 rows.
#define M_ROWS 4096
#define C_DIM  768
#define T_SEQ  2048
#define H_HEADS 12
#define D_HEAD 64
#define QKV_LD (3*C_DIM)   // 2304
#define FC_DIM (4*C_DIM)   // 3072

// ---------------- scratch (device globals: no allocation allowed) -------------
__device__ __half g_xn [M_ROWS * C_DIM];
__device__ __half g_qkv[M_ROWS * QKV_LD];   // fp16 natural layout
__device__ __half g_y  [M_ROWS * C_DIM];
__device__ float  g_x2 [M_ROWS * C_DIM];
__device__ __half g_h  [M_ROWS * FC_DIM];
// transposed (K-major, fp16, k-permuted) weights
__device__ __half g_wattnT[QKV_LD * C_DIM];
__device__ __half g_wprojT[C_DIM * C_DIM];
__device__ __half g_wfcT  [FC_DIM * C_DIM];
__device__ __half g_wmlpT [C_DIM * FC_DIM];

// ======================= helpers ==============================================
__device__ __forceinline__ uint32_t smem_u32(const void* p) {
    uint32_t a;
    asm("{ .reg .u64 t; cvta.to.shared.u64 t, %1; cvt.u32.u64 %0, t; }" : "=r"(a) : "l"(p));
    return a;
}
__device__ __forceinline__ void cp_async16(uint32_t s, const void* g) {
    asm volatile("cp.async.cg.shared.global [%0], [%1], 16;" :: "r"(s), "l"(g));
}
#define CP_COMMIT() asm volatile("cp.async.commit_group;" ::: "memory")
#define CP_WAIT(n)  asm volatile("cp.async.wait_group %0;" :: "n"(n) : "memory")

// permute k within 16-groups: a thread's mma fragment halves
// {2t4, 2t4+1, 2t4+8, 2t4+9} become 4 contiguous halves at 16g + 4*t4.
__device__ __forceinline__ int perm16(int k) {
    int lo = k & 15;
    int p = ((lo & 7) >> 1) * 4 + ((lo >> 3) << 1) + (lo & 1);
    return (k & ~15) | p;
}
// smem half-index for tile row r, half col k; 16B-unit XOR swizzle
__device__ __forceinline__ int haddr(int r, int k) {
    int u = k >> 3;
    return r * 64 + (((u ^ (r & 7)) << 3) | (k & 7));
}
// D(16x8,f32) += A(16x16,f16) * B(16x8,f16)
__device__ __forceinline__ void mma_f16(float* d, const uint32_t* a, const uint32_t* b) {
    asm volatile(
        "mma.sync.aligned.m16n8k16.row.col.f32.f16.f16.f32 "
        "{%0,%1,%2,%3}, {%4,%5,%6,%7}, {%8,%9}, {%0,%1,%2,%3};"
        : "+f"(d[0]), "+f"(d[1]), "+f"(d[2]), "+f"(d[3])
        : "r"(a[0]), "r"(a[1]), "r"(a[2]), "r"(a[3]), "r"(b[0]), "r"(b[1]));
}
#define LDMX4(r, addr) \
    asm volatile("ldmatrix.sync.aligned.m8n8.x4.shared.b16 {%0,%1,%2,%3}, [%4];" \
        : "=r"((r)[0]), "=r"((r)[1]), "=r"((r)[2]), "=r"((r)[3]) : "r"(addr))
#define LDMX4T(r, addr) \
    asm volatile("ldmatrix.sync.aligned.m8n8.x4.trans.shared.b16 {%0,%1,%2,%3}, [%4];" \
        : "=r"((r)[0]), "=r"((r)[1]), "=r"((r)[2]), "=r"((r)[3]) : "r"(addr))

// ---------------- LayerNorm (output: fp16, k-permuted) ------------------------
__global__ __launch_bounds__(256) void ln_kernel(const float* __restrict__ x,
                                                 const float* __restrict__ w,
                                                 __half* __restrict__ out) {
    int row = blockIdx.x;
    const float* xr = x + (size_t)row * C_DIM;
    float s = 0.f, s2 = 0.f;
    for (int i = threadIdx.x; i < C_DIM; i += 256) {
        float v = xr[i];
        s += v; s2 += v * v;
    }
    #pragma unroll
    for (int o = 16; o; o >>= 1) {
        s  += __shfl_xor_sync(0xFFFFFFFFu, s,  o);
        s2 += __shfl_xor_sync(0xFFFFFFFFu, s2, o);
    }
    __shared__ float ss[8], ss2[8];
    int wid = threadIdx.x >> 5, lid = threadIdx.x & 31;
    if (lid == 0) { ss[wid] = s; ss2[wid] = s2; }
    __syncthreads();
    if (wid == 0) {
        s  = (lid < 8) ? ss[lid]  : 0.f;
        s2 = (lid < 8) ? ss2[lid] : 0.f;
        #pragma unroll
        for (int o = 4; o; o >>= 1) {
            s  += __shfl_xor_sync(0xFFFFFFFFu, s,  o);
            s2 += __shfl_xor_sync(0xFFFFFFFFu, s2, o);
        }
        if (lid == 0) { ss[0] = s; ss2[0] = s2; }
    }
    __syncthreads();
    float mean = ss[0] * (1.f / C_DIM);
    float var  = ss2[0] * (1.f / C_DIM) - mean * mean;
    float inv  = rsqrtf(var + 1e-5f);
    for (int i = threadIdx.x; i < C_DIM; i += 256)
        out[(size_t)row * C_DIM + perm16(i)] = __float2half((xr[i] - mean) * inv * w[i]);
}

// ---------------- Weight transpose -> fp16, k-permuted ------------------------
__global__ __launch_bounds__(256) void transpose_h_kernel(const float* __restrict__ in,
                                                          __half* __restrict__ out,
                                                          int rows, int cols) {
    __shared__ float tile[32][33];
    int bx = blockIdx.x * 32;
    int by = blockIdx.y * 32;
    int x = bx + threadIdx.x;
    #pragma unroll
    for (int j = 0; j < 32; j += 8)
        tile[threadIdx.y + j][threadIdx.x] = in[(size_t)(by + threadIdx.y + j) * cols + x];
    __syncthreads();
    int ox = by + threadIdx.x;
    #pragma unroll
    for (int j = 0; j < 32; j += 8) {
        float v = tile[threadIdx.x][threadIdx.y + j];
        out[(size_t)(bx + threadIdx.y + j) * rows + perm16(ox)] = __float2half(v);
    }
}

// ---------------- fp16 mma GEMM, 128x256 CTA tile, warp tile 64x64 ------------
// MODE 0: C = A@B -> fp16 natural ; MODE 1: C = A@B + R -> f32 ;
// MODE 2: C = gelu(A@B) -> fp16, k-permuted
#define STAGE_H 24576                        // (128 + 256) * 64 halves
#define GEMM_SMEM_BYTES (3 * STAGE_H * 2)    // 147456

template<int MODE>
__global__ __launch_bounds__(256, 1) void mma_gemm_kernel(
    const __half* __restrict__ A, const __half* __restrict__ BT,
    const float* __restrict__ R, void* __restrict__ Cv,
    int M, int N, int K)
{
    extern __shared__ __half smh[];
    uint32_t sm_u = smem_u32(smh);

    int tid  = threadIdx.x;
    int wid  = tid >> 5, lane = tid & 31;
    int wm   = wid & 1;
    int wn   = wid >> 1;
    int g    = lane >> 2, t4 = lane & 3;
    int m0 = blockIdx.y * 128, n0 = blockIdx.x * 256;

    float acc[4][8][4];
    #pragma unroll
    for (int i = 0; i < 4; i++)
        #pragma unroll
        for (int j = 0; j < 8; j++)
            #pragma unroll
            for (int q = 0; q < 4; q++) acc[i][j][q] = 0.f;

    const int nch = K >> 6;

    auto issue = [&](int k0, int s) {
        uint32_t sb = sm_u + (uint32_t)(s * STAGE_H) * 2;
        #pragma unroll
        for (int t = 0; t < 4; t++) {
            int idx = t * 256 + tid;
            int row = idx >> 3, u = idx & 7;
            cp_async16(sb + (uint32_t)(row * 64 + ((u ^ (row & 7)) << 3)) * 2,
                       A + (size_t)(m0 + row) * K + k0 + u * 8);
        }
        uint32_t bb = sb + 8192u * 2;
        #pragma unroll
        for (int t = 0; t < 8; t++) {
            int idx = t * 256 + tid;
            int row = idx >> 3, u = idx & 7;
            cp_async16(bb + (uint32_t)(row * 64 + ((u ^ (row & 7)) << 3)) * 2,
                       BT + (size_t)(n0 + row) * K + k0 + u * 8);
        }
    };

    issue(0, 0); CP_COMMIT();
    if (nch > 1) { issue(64, 1); CP_COMMIT(); }

    for (int ic = 0; ic < nch; ic++) {
        if (ic + 2 < nch) { issue((ic + 2) * 64, (ic + 2) % 3); CP_COMMIT(); }
        int pend = nch - 1 - ic;
        if (pend >= 2)      CP_WAIT(2);
        else if (pend == 1) CP_WAIT(1);
        else                CP_WAIT(0);
        __syncthreads();

        const __half* Ah = smh + (ic % 3) * STAGE_H;
        const __half* Bh = Ah + 8192;
        #pragma unroll
        for (int ks = 0; ks < 4; ks++) {
            uint32_t a[4][4], b[8][2];
            int kc = ks * 16 + 4 * t4;
            #pragma unroll
            for (int mt = 0; mt < 4; mt++) {
                int r = wm * 64 + mt * 16 + g;
                uint2 lo = *(const uint2*)(Ah + haddr(r,     kc));
                uint2 hi = *(const uint2*)(Ah + haddr(r + 8, kc));
                a[mt][0] = lo.x; a[mt][2] = lo.y;
                a[mt][1] = hi.x; a[mt][3] = hi.y;
            }
            #pragma unroll
            for (int nt = 0; nt < 8; nt++) {
                int nr = wn * 64 + nt * 8 + g;
                uint2 bv = *(const uint2*)(Bh + haddr(nr, kc));
                b[nt][0] = bv.x; b[nt][1] = bv.y;
            }
            #pragma unroll
            for (int mt = 0; mt < 4; mt++)
                #pragma unroll
                for (int nt = 0; nt < 8; nt++)
                    mma_f16(acc[mt][nt], a[mt], b[nt]);
        }
        __syncthreads();
    }

    #pragma unroll
    for (int mt = 0; mt < 4; mt++) {
        int r0 = m0 + wm * 64 + mt * 16 + g;
        #pragma unroll
        for (int nt = 0; nt < 8; nt++) {
            int c = n0 + wn * 64 + nt * 8 + 2 * t4;
            #pragma unroll
            for (int half_ = 0; half_ < 2; half_++) {
                int r = r0 + half_ * 8;
                float v0 = acc[mt][nt][half_ * 2 + 0];
                float v1 = acc[mt][nt][half_ * 2 + 1];
                if (MODE == 1) {
                    float* C = (float*)Cv;
                    float2 rv = *(const float2*)(R + (size_t)r * N + c);
                    v0 += rv.x; v1 += rv.y;
                    *(float2*)(C + (size_t)r * N + c) = make_float2(v0, v1);
                } else if (MODE == 2) {
                    __half* C = (__half*)Cv;
                    v0 = 0.5f * v0 * (1.0f + erff(v0 * 0.70710678118654752f));
                    v1 = 0.5f * v1 * (1.0f + erff(v1 * 0.70710678118654752f));
                    C[(size_t)r * N + perm16(c)]     = __float2half(v0);
                    C[(size_t)r * N + perm16(c + 1)] = __float2half(v1);
                } else {
                    __half* C = (__half*)Cv;
                    *(__half2*)(C + (size_t)r * N + c) = __floats2half2_rn(v0, v1);
                }
            }
        }
    }
}

// ---------------- Attention: fp16 mma, 128q blocks, 64k tiles -----------------
// scores = exp(-(q2+k2-2qk)/(2 sqrt(D))), causal, unnormalized. y: fp16 perm16.
#define ATTN_SMEM_BYTES (24576 * 2 + 256 * 4)

__global__ __launch_bounds__(256, 2) void attn_kernel(const __half* __restrict__ qkv,
                                                      __half* __restrict__ y) {
    int qi = blockIdx.x, h = blockIdx.y, b = blockIdx.z;
    extern __shared__ __half smh[];
    __half* Qs = smh;                 // 128 x 64
    __half* Ks = smh + 8192;          // 2 x 64 x 64
    __half* Vs = smh + 16384;         // 2 x 64 x 64
    float* q2s = (float*)(smh + 24576);   // 128
    float* k2s = q2s + 128;               // 2 x 64
    uint32_t Qu = smem_u32(Qs), Ku = smem_u32(Ks), Vu = smem_u32(Vs);

    int tid = threadIdx.x, wid = tid >> 5, lane = tid & 31;
    int g = lane >> 2, t4 = lane & 3;
    int qrow0 = wid * 16;
    const float scale = -0.0625f;     // -1/(2*sqrt(64))

    // load Q (128 rows x 8 units)
    {
        const __half* qg = qkv + ((size_t)(b * T_SEQ + qi * 128)) * QKV_LD + h * 64;
        #pragma unroll
        for (int t = 0; t < 4; t++) {
            int idx = t * 256 + tid;
            int r = idx >> 3, u = idx & 7;
            cp_async16(Qu + (uint32_t)(r * 64 + ((u ^ (r & 7)) << 3)) * 2,
                       qg + (size_t)r * QKV_LD + u * 8);
        }
    }
    auto loadKV = [&](int kt, int bb) {
        const __half* kg = qkv + ((size_t)(b * T_SEQ + kt * 64)) * QKV_LD + C_DIM + h * 64;
        const __half* vg = kg + C_DIM;
        uint32_t kb = Ku + (uint32_t)(bb * 4096) * 2;
        uint32_t vb = Vu + (uint32_t)(bb * 4096) * 2;
        #pragma unroll
        for (int t = 0; t < 2; t++) {
            int idx = t * 256 + tid;
            int r = idx >> 3, u = idx & 7;
            uint32_t so = (uint32_t)(r * 64 + ((u ^ (r & 7)) << 3)) * 2;
            cp_async16(kb + so, kg + (size_t)r * QKV_LD + u * 8);
            cp_async16(vb + so, vg + (size_t)r * QKV_LD + u * 8);
        }
    };
    loadKV(0, 0); CP_COMMIT();

    int nkt = 2 * qi + 2;
    uint32_t qf[4][4];
    float oacc[8][4];
    #pragma unroll
    for (int i = 0; i < 8; i++)
        #pragma unroll
        for (int q = 0; q < 4; q++) oacc[i][q] = 0.f;

    int qg0 = qi * 128 + qrow0 + g;
    int qg1 = qg0 + 8;
    float q2a = 0.f, q2b = 0.f;

    for (int kt = 0; kt < nkt; kt++) {
        int buf = kt & 1;
        if (kt + 1 < nkt) { loadKV(kt + 1, buf ^ 1); CP_COMMIT(); CP_WAIT(1); }
        else              { CP_WAIT(0); }
        __syncthreads();

        if (kt == 0 && tid < 128) {        // q2
            int r = tid;
            float s = 0.f;
            #pragma unroll
            for (int u = 0; u < 8; u++) {
                uint4 v = *(const uint4*)(Qs + r * 64 + ((u ^ (r & 7)) << 3));
                const uint32_t* w = &v.x;
                #pragma unroll
                for (int j = 0; j < 4; j++) {
                    float2 f = __half22float2(*(const __half2*)&w[j]);
                    s += f.x * f.x + f.y * f.y;
                }
            }
            q2s[r] = s;
        }
        if (tid >= 128 && tid < 192) {     // k2 for this buffer
            int r = tid - 128;
            const __half* kb = Ks + buf * 4096;
            float s = 0.f;
            #pragma unroll
            for (int u = 0; u < 8; u++) {
                uint4 v = *(const uint4*)(kb + r * 64 + ((u ^ (r & 7)) << 3));
                const uint32_t* w = &v.x;
                #pragma unroll
                for (int j = 0; j < 4; j++) {
                    float2 f = __half22float2(*(const __half2*)&w[j]);
                    s += f.x * f.x + f.y * f.y;
                }
            }
            k2s[buf * 64 + r] = s;
        }
        __syncthreads();

        if (kt == 0) {
            // Q fragments once per block
            #pragma unroll
            for (int ks = 0; ks < 4; ks++) {
                int m = lane >> 3;
                int r = qrow0 + ((m & 1) << 3) + (lane & 7);
                int d0 = ks * 16 + ((m >> 1) << 3);
                LDMX4(qf[ks], Qu + (uint32_t)haddr(r, d0) * 2);
            }
            q2a = q2s[qrow0 + g];
            q2b = q2s[qrow0 + g + 8];
        }

        uint32_t kbase = Ku + (uint32_t)(buf * 4096) * 2;
        uint32_t vbase = Vu + (uint32_t)(buf * 4096) * 2;

        // ---- S = Q @ K^T ----
        float sacc[8][4];
        #pragma unroll
        for (int i = 0; i < 8; i++)
            #pragma unroll
            for (int q = 0; q < 4; q++) sacc[i][q] = 0.f;
        #pragma unroll
        for (int ks = 0; ks < 4; ks++) {
            uint32_t kf[4][4];
            #pragma unroll
            for (int nt2 = 0; nt2 < 4; nt2++) {
                int m = lane >> 3;
                int tok = nt2 * 16 + ((m >> 1) << 3) + (lane & 7);
                int d0 = ks * 16 + ((m & 1) << 3);
                LDMX4(kf[nt2], kbase + (uint32_t)haddr(tok, d0) * 2);
            }
            #pragma unroll
            for (int nt2 = 0; nt2 < 4; nt2++) {
                mma_f16(sacc[2 * nt2],     qf[ks], &kf[nt2][0]);
                mma_f16(sacc[2 * nt2 + 1], qf[ks], &kf[nt2][2]);
            }
        }

        // ---- scores -> P (fp16 in registers) ----
        uint32_t ph[8], ph2[8];
        int kc0 = kt * 64 + 2 * t4;
        #pragma unroll
        for (int nt = 0; nt < 8; nt++) {
            int c0 = kc0 + nt * 8;
            float k2a = k2s[buf * 64 + nt * 8 + 2 * t4];
            float k2b = k2s[buf * 64 + nt * 8 + 2 * t4 + 1];
            float e00 = (c0     <= qg0) ? __expf(scale * (q2a + k2a - 2.f * sacc[nt][0])) : 0.f;
            float e01 = (c0 + 1 <= qg0) ? __expf(scale * (q2a + k2b - 2.f * sacc[nt][1])) : 0.f;
            float e10 = (c0     <= qg1) ? __expf(scale * (q2b + k2a - 2.f * sacc[nt][2])) : 0.f;
            float e11 = (c0 + 1 <= qg1) ? __expf(scale * (q2b + k2b - 2.f * sacc[nt][3])) : 0.f;
            __half2 p0 = __floats2half2_rn(e00, e01);
            __half2 p1 = __floats2half2_rn(e10, e11);
            ph[nt]  = *(uint32_t*)&p0;
            ph2[nt] = *(uint32_t*)&p1;
        }

        // ---- O += P @ V ----
        #pragma unroll
        for (int kc = 0; kc < 4; kc++) {
            uint32_t vf[4][4];
            #pragma unroll
            for (int dn2 = 0; dn2 < 4; dn2++) {
                int m = lane >> 3;
                int tok = kc * 16 + ((m & 1) << 3) + (lane & 7);
                int d0 = dn2 * 16 + ((m >> 1) << 3);
                LDMX4T(vf[dn2], vbase + (uint32_t)haddr(tok, d0) * 2);
            }
            uint32_t a[4] = { ph[2 * kc], ph2[2 * kc], ph[2 * kc + 1], ph2[2 * kc + 1] };
            #pragma unroll
            for (int dn2 = 0; dn2 < 4; dn2++) {
                mma_f16(oacc[2 * dn2],     a, &vf[dn2][0]);
                mma_f16(oacc[2 * dn2 + 1], a, &vf[dn2][2]);
            }
        }
        __syncthreads();
    }

    // ---- write y (fp16, perm16) ----
    size_t row0 = (size_t)(b * T_SEQ + qi * 128 + qrow0 + g);
    #pragma unroll
    for (int dn = 0; dn < 8; dn++) {
        int col = h * 64 + dn * 8 + 2 * t4;
        int pc = perm16(col);
        __half2 v0 = __floats2half2_rn(oacc[dn][0], oacc[dn][1]);
        __half2 v1 = __floats2half2_rn(oacc[dn][2], oacc[dn][3]);
        *(__half2*)(y + row0 * C_DIM + pc)       = v0;
        *(__half2*)(y + (row0 + 8) * C_DIM + pc) = v1;
    }
}

// ---------------- launch ------------------------------------------------------
extern "C" void kernel_launch(void* const* d_in, const int* in_sizes, int n_in,
                              void* d_out, int out_size) {
    const float* x           = (const float*)d_in[0];
    const float* w_ln1       = (const float*)d_in[1];
    const float* w_attn      = (const float*)d_in[2];
    const float* w_attn_proj = (const float*)d_in[3];
    const float* w_ln2       = (const float*)d_in[4];
    const float* w_fc        = (const float*)d_in[5];
    const float* w_mlp_proj  = (const float*)d_in[6];
    float* out = (float*)d_out;

    __half *xn, *qkv, *y, *hbuf, *wattnT, *wprojT, *wfcT, *wmlpT;
    float *x2;
    cudaGetSymbolAddress((void**)&xn,     g_xn);
    cudaGetSymbolAddress((void**)&qkv,    g_qkv);
    cudaGetSymbolAddress((void**)&y,      g_y);
    cudaGetSymbolAddress((void**)&x2,     g_x2);
    cudaGetSymbolAddress((void**)&hbuf,   g_h);
    cudaGetSymbolAddress((void**)&wattnT, g_wattnT);
    cudaGetSymbolAddress((void**)&wprojT, g_wprojT);
    cudaGetSymbolAddress((void**)&wfcT,   g_wfcT);
    cudaGetSymbolAddress((void**)&wmlpT,  g_wmlpT);

    cudaFuncSetAttribute(attn_kernel, cudaFuncAttributeMaxDynamicSharedMemorySize, ATTN_SMEM_BYTES);
    cudaFuncSetAttribute(mma_gemm_kernel<0>, cudaFuncAttributeMaxDynamicSharedMemorySize, GEMM_SMEM_BYTES);
    cudaFuncSetAttribute(mma_gemm_kernel<1>, cudaFuncAttributeMaxDynamicSharedMemorySize, GEMM_SMEM_BYTES);
    cudaFuncSetAttribute(mma_gemm_kernel<2>, cudaFuncAttributeMaxDynamicSharedMemorySize, GEMM_SMEM_BYTES);

    dim3 tb(32, 8);
    transpose_h_kernel<<<dim3(QKV_LD / 32, C_DIM / 32), tb>>>(w_attn,      wattnT, C_DIM,  QKV_LD);
    transpose_h_kernel<<<dim3(C_DIM / 32,  C_DIM / 32), tb>>>(w_attn_proj, wprojT, C_DIM,  C_DIM);
    transpose_h_kernel<<<dim3(FC_DIM / 32, C_DIM / 32), tb>>>(w_fc,        wfcT,   C_DIM,  FC_DIM);
    transpose_h_kernel<<<dim3(C_DIM / 32,  FC_DIM / 32), tb>>>(w_mlp_proj, wmlpT,  FC_DIM, C_DIM);

    // 1. ln1(x) -> xn  (fp16, k-permuted)
    ln_kernel<<<M_ROWS, 256>>>(x, w_ln1, xn);
    // 2. qkv = xn @ w_attn  (fp16 natural out)
    mma_gemm_kernel<0><<<dim3(QKV_LD / 256, M_ROWS / 128), 256, GEMM_SMEM_BYTES>>>(
        xn, wattnT, nullptr, qkv, M_ROWS, QKV_LD, C_DIM);
    // 3. attention -> y (fp16, k-permuted)
    attn_kernel<<<dim3(T_SEQ / 128, H_HEADS, 2), 256, ATTN_SMEM_BYTES>>>(qkv, y);
    // 4. x2 = y @ w_attn_proj + x  (f32 out)
    mma_gemm_kernel<1><<<dim3(C_DIM / 256, M_ROWS / 128), 256, GEMM_SMEM_BYTES>>>(
        y, wprojT, x, x2, M_ROWS, C_DIM, C_DIM);
    // 5. ln2(x2) -> xn
    ln_kernel<<<M_ROWS, 256>>>(x2, w_ln2, xn);
    // 6. h = gelu(xn @ w_fc)  (fp16, k-permuted)
    mma_gemm_kernel<2><<<dim3(FC_DIM / 256, M_ROWS / 128), 256, GEMM_SMEM_BYTES>>>(
        xn, wfcT, nullptr, hbuf, M_ROWS, FC_DIM, C_DIM);
    // 7. out = h @ w_mlp_proj + x2  (f32 out)
    mma_gemm_kernel<1><<<dim3(C_DIM / 256, M_ROWS / 128), 256, GEMM_SMEM_BYTES>>>(
        hbuf, wmlpT, x2, out, M_ROWS, C_DIM, FC_DIM);
}

// round 8
// speedup vs baseline: 3.1737x; 1.0264x over previous
#include <cuda_runtime.h>
#include <cuda_fp16.h>
#include <math.h>
#include <cstdint>

// Problem: B=2, T=2048, C=768, H=12, D=64.  M = B*T = 4096 rows.
#define M_ROWS 4096
#define C_DIM  768
#define T_SEQ  2048
#define H_HEADS 12
#define D_HEAD 64
#define QKV_LD (3*C_DIM)   // 2304
#define FC_DIM (4*C_DIM)   // 3072

// ---------------- scratch (device globals: no allocation allowed) -------------
__device__ __half g_xn [M_ROWS * C_DIM];
__device__ __half g_qkv[M_ROWS * QKV_LD];   // fp16 natural layout
__device__ __half g_y  [M_ROWS * C_DIM];
__device__ float  g_x2 [M_ROWS * C_DIM];
__device__ __half g_h  [M_ROWS * FC_DIM];
// transposed (K-major, fp16, k-permuted) weights
__device__ __half g_wattnT[QKV_LD * C_DIM];
__device__ __half g_wprojT[C_DIM * C_DIM];
__device__ __half g_wfcT  [FC_DIM * C_DIM];
__device__ __half g_wmlpT [C_DIM * FC_DIM];

// ======================= helpers ==============================================
__device__ __forceinline__ uint32_t smem_u32(const void* p) {
    uint32_t a;
    asm("{ .reg .u64 t; cvta.to.shared.u64 t, %1; cvt.u32.u64 %0, t; }" : "=r"(a) : "l"(p));
    return a;
}
__device__ __forceinline__ void cp_async16(uint32_t s, const void* g) {
    asm volatile("cp.async.cg.shared.global [%0], [%1], 16;" :: "r"(s), "l"(g));
}
#define CP_COMMIT() asm volatile("cp.async.commit_group;" ::: "memory")
#define CP_WAIT(n)  asm volatile("cp.async.wait_group %0;" :: "n"(n) : "memory")

// permute k within 16-groups: a thread's mma fragment halves
// {2t4, 2t4+1, 2t4+8, 2t4+9} become 4 contiguous halves at 16g + 4*t4.
__device__ __forceinline__ int perm16(int k) {
    int lo = k & 15;
    int p = ((lo & 7) >> 1) * 4 + ((lo >> 3) << 1) + (lo & 1);
    return (k & ~15) | p;
}
// smem half-index for tile row r, half col k; 16B-unit XOR swizzle
__device__ __forceinline__ int haddr(int r, int k) {
    int u = k >> 3;
    return r * 64 + (((u ^ (r & 7)) << 3) | (k & 7));
}
// D(16x8,f32) += A(16x16,f16) * B(16x8,f16)
__device__ __forceinline__ void mma_f16(float* d, const uint32_t* a, const uint32_t* b) {
    asm volatile(
        "mma.sync.aligned.m16n8k16.row.col.f32.f16.f16.f32 "
        "{%0,%1,%2,%3}, {%4,%5,%6,%7}, {%8,%9}, {%0,%1,%2,%3};"
        : "+f"(d[0]), "+f"(d[1]), "+f"(d[2]), "+f"(d[3])
        : "r"(a[0]), "r"(a[1]), "r"(a[2]), "r"(a[3]), "r"(b[0]), "r"(b[1]));
}
#define LDMX4(r, addr) \
    asm volatile("ldmatrix.sync.aligned.m8n8.x4.shared.b16 {%0,%1,%2,%3}, [%4];" \
        : "=r"((r)[0]), "=r"((r)[1]), "=r"((r)[2]), "=r"((r)[3]) : "r"(addr))
#define LDMX4T(r, addr) \
    asm volatile("ldmatrix.sync.aligned.m8n8.x4.trans.shared.b16 {%0,%1,%2,%3}, [%4];" \
        : "=r"((r)[0]), "=r"((r)[1]), "=r"((r)[2]), "=r"((r)[3]) : "r"(addr))

// ---------------- LayerNorm (output: fp16, k-permuted) ------------------------
__global__ __launch_bounds__(256) void ln_kernel(const float* __restrict__ x,
                                                 const float* __restrict__ w,
                                                 __half* __restrict__ out) {
    int row = blockIdx.x;
    const float* xr = x + (size_t)row * C_DIM;
    float s = 0.f, s2 = 0.f;
    for (int i = threadIdx.x; i < C_DIM; i += 256) {
        float v = xr[i];
        s += v; s2 += v * v;
    }
    #pragma unroll
    for (int o = 16; o; o >>= 1) {
        s  += __shfl_xor_sync(0xFFFFFFFFu, s,  o);
        s2 += __shfl_xor_sync(0xFFFFFFFFu, s2, o);
    }
    __shared__ float ss[8], ss2[8];
    int wid = threadIdx.x >> 5, lid = threadIdx.x & 31;
    if (lid == 0) { ss[wid] = s; ss2[wid] = s2; }
    __syncthreads();
    if (wid == 0) {
        s  = (lid < 8) ? ss[lid]  : 0.f;
        s2 = (lid < 8) ? ss2[lid] : 0.f;
        #pragma unroll
        for (int o = 4; o; o >>= 1) {
            s  += __shfl_xor_sync(0xFFFFFFFFu, s,  o);
            s2 += __shfl_xor_sync(0xFFFFFFFFu, s2, o);
        }
        if (lid == 0) { ss[0] = s; ss2[0] = s2; }
    }
    __syncthreads();
    float mean = ss[0] * (1.f / C_DIM);
    float var  = ss2[0] * (1.f / C_DIM) - mean * mean;
    float inv  = rsqrtf(var + 1e-5f);
    for (int i = threadIdx.x; i < C_DIM; i += 256)
        out[(size_t)row * C_DIM + perm16(i)] = __float2half((xr[i] - mean) * inv * w[i]);
}

// ---------------- All 4 weight transposes in one launch ------------------------
// segment tile counts: wattn 72x24, wproj 24x24, wfc 96x24, wmlp 24x96
#define SEG0 1728
#define SEG1 (SEG0 + 576)
#define SEG2 (SEG1 + 2304)
#define SEG3 (SEG2 + 2304)    // 6912 total

__global__ __launch_bounds__(256) void transpose_all_kernel(
    const float* __restrict__ in0, __half* __restrict__ out0,
    const float* __restrict__ in1, __half* __restrict__ out1,
    const float* __restrict__ in2, __half* __restrict__ out2,
    const float* __restrict__ in3, __half* __restrict__ out3)
{
    int bid = blockIdx.x;
    const float* in; __half* out; int rows, cols, t0, ntx;
    if (bid < SEG0)      { in = in0; out = out0; rows = C_DIM;  cols = QKV_LD; t0 = 0;    ntx = QKV_LD / 32; }
    else if (bid < SEG1) { in = in1; out = out1; rows = C_DIM;  cols = C_DIM;  t0 = SEG0; ntx = C_DIM / 32; }
    else if (bid < SEG2) { in = in2; out = out2; rows = C_DIM;  cols = FC_DIM; t0 = SEG1; ntx = FC_DIM / 32; }
    else                 { in = in3; out = out3; rows = FC_DIM; cols = C_DIM;  t0 = SEG2; ntx = C_DIM / 32; }
    int t = bid - t0;
    int bx = (t % ntx) * 32;
    int by = (t / ntx) * 32;

    __shared__ float tile[32][33];
    int tx = threadIdx.x & 31, ty = threadIdx.x >> 5;
    int x = bx + tx;
    #pragma unroll
    for (int j = 0; j < 32; j += 8)
        tile[ty + j][tx] = in[(size_t)(by + ty + j) * cols + x];
    __syncthreads();
    int ox = by + tx;
    #pragma unroll
    for (int j = 0; j < 32; j += 8) {
        float v = tile[tx][ty + j];
        out[(size_t)(bx + ty + j) * rows + perm16(ox)] = __float2half(v);
    }
}

// ---------------- fp16 mma GEMM, 128x256 CTA tile, warp tile 64x64 ------------
// MODE 0: C = A@B -> fp16 natural ; MODE 1: C = A@B + R -> f32 ;
// MODE 2: C = gelu(A@B) -> fp16, k-permuted
#define STAGE_H 24576                        // (128 + 256) * 64 halves
#define GEMM_SMEM_BYTES (3 * STAGE_H * 2)    // 147456

template<int MODE>
__global__ __launch_bounds__(256, 1) void mma_gemm_kernel(
    const __half* __restrict__ A, const __half* __restrict__ BT,
    const float* __restrict__ R, void* __restrict__ Cv,
    int M, int N, int K)
{
    extern __shared__ __half smh[];
    uint32_t sm_u = smem_u32(smh);

    int tid  = threadIdx.x;
    int wid  = tid >> 5, lane = tid & 31;
    int wm   = wid & 1;
    int wn   = wid >> 1;
    int g    = lane >> 2, t4 = lane & 3;
    int m0 = blockIdx.y * 128, n0 = blockIdx.x * 256;

    float acc[4][8][4];
    #pragma unroll
    for (int i = 0; i < 4; i++)
        #pragma unroll
        for (int j = 0; j < 8; j++)
            #pragma unroll
            for (int q = 0; q < 4; q++) acc[i][j][q] = 0.f;

    const int nch = K >> 6;

    auto issue = [&](int k0, int s) {
        uint32_t sb = sm_u + (uint32_t)(s * STAGE_H) * 2;
        #pragma unroll
        for (int t = 0; t < 4; t++) {
            int idx = t * 256 + tid;
            int row = idx >> 3, u = idx & 7;
            cp_async16(sb + (uint32_t)(row * 64 + ((u ^ (row & 7)) << 3)) * 2,
                       A + (size_t)(m0 + row) * K + k0 + u * 8);
        }
        uint32_t bb = sb + 8192u * 2;
        #pragma unroll
        for (int t = 0; t < 8; t++) {
            int idx = t * 256 + tid;
            int row = idx >> 3, u = idx & 7;
            cp_async16(bb + (uint32_t)(row * 64 + ((u ^ (row & 7)) << 3)) * 2,
                       BT + (size_t)(n0 + row) * K + k0 + u * 8);
        }
    };

    issue(0, 0); CP_COMMIT();
    if (nch > 1) { issue(64, 1); CP_COMMIT(); }

    for (int ic = 0; ic < nch; ic++) {
        // wait for stage ic (outstanding groups beyond it: at most 1 here)
        if (ic + 1 < nch) CP_WAIT(1);
        else              CP_WAIT(0);
        __syncthreads();   // all warps done with math of ic-1 -> safe to refill its stage
        if (ic + 2 < nch) { issue((ic + 2) * 64, (ic + 2) % 3); CP_COMMIT(); }

        const __half* Ah = smh + (ic % 3) * STAGE_H;
        const __half* Bh = Ah + 8192;
        #pragma unroll
        for (int ks = 0; ks < 4; ks++) {
            uint32_t a[4][4], b[8][2];
            int kc = ks * 16 + 4 * t4;
            #pragma unroll
            for (int mt = 0; mt < 4; mt++) {
                int r = wm * 64 + mt * 16 + g;
                uint2 lo = *(const uint2*)(Ah + haddr(r,     kc));
                uint2 hi = *(const uint2*)(Ah + haddr(r + 8, kc));
                a[mt][0] = lo.x; a[mt][2] = lo.y;
                a[mt][1] = hi.x; a[mt][3] = hi.y;
            }
            #pragma unroll
            for (int nt = 0; nt < 8; nt++) {
                int nr = wn * 64 + nt * 8 + g;
                uint2 bv = *(const uint2*)(Bh + haddr(nr, kc));
                b[nt][0] = bv.x; b[nt][1] = bv.y;
            }
            #pragma unroll
            for (int mt = 0; mt < 4; mt++)
                #pragma unroll
                for (int nt = 0; nt < 8; nt++)
                    mma_f16(acc[mt][nt], a[mt], b[nt]);
        }
    }

    #pragma unroll
    for (int mt = 0; mt < 4; mt++) {
        int r0 = m0 + wm * 64 + mt * 16 + g;
        #pragma unroll
        for (int nt = 0; nt < 8; nt++) {
            int c = n0 + wn * 64 + nt * 8 + 2 * t4;
            #pragma unroll
            for (int half_ = 0; half_ < 2; half_++) {
                int r = r0 + half_ * 8;
                float v0 = acc[mt][nt][half_ * 2 + 0];
                float v1 = acc[mt][nt][half_ * 2 + 1];
                if (MODE == 1) {
                    float* C = (float*)Cv;
                    float2 rv = *(const float2*)(R + (size_t)r * N + c);
                    v0 += rv.x; v1 += rv.y;
                    *(float2*)(C + (size_t)r * N + c) = make_float2(v0, v1);
                } else if (MODE == 2) {
                    __half* C = (__half*)Cv;
                    v0 = 0.5f * v0 * (1.0f + erff(v0 * 0.70710678118654752f));
                    v1 = 0.5f * v1 * (1.0f + erff(v1 * 0.70710678118654752f));
                    C[(size_t)r * N + perm16(c)]     = __float2half(v0);
                    C[(size_t)r * N + perm16(c + 1)] = __float2half(v1);
                } else {
                    __half* C = (__half*)Cv;
                    *(__half2*)(C + (size_t)r * N + c) = __floats2half2_rn(v0, v1);
                }
            }
        }
    }
}

// ---------------- Attention: fp16 mma, 128q blocks, 64k tiles -----------------
// scores = exp(-(q2+k2-2qk)/(2 sqrt(D))), causal, unnormalized. y: fp16 perm16.
#define ATTN_SMEM_BYTES (24576 * 2 + 256 * 4)

__global__ __launch_bounds__(256, 2) void attn_kernel(const __half* __restrict__ qkv,
                                                      __half* __restrict__ y) {
    // big CTAs (largest qi) first: better wave balance under causal skew
    int qi = gridDim.x - 1 - blockIdx.x;
    int h = blockIdx.y, b = blockIdx.z;
    extern __shared__ __half smh[];
    __half* Qs = smh;                 // 128 x 64
    __half* Ks = smh + 8192;          // 2 x 64 x 64
    __half* Vs = smh + 16384;         // 2 x 64 x 64
    float* q2s = (float*)(smh + 24576);   // 128
    float* k2s = q2s + 128;               // 2 x 64
    uint32_t Qu = smem_u32(Qs), Ku = smem_u32(Ks), Vu = smem_u32(Vs);

    int tid = threadIdx.x, wid = tid >> 5, lane = tid & 31;
    int g = lane >> 2, t4 = lane & 3;
    int qrow0 = wid * 16;
    const float scale = -0.0625f;     // -1/(2*sqrt(64))

    // load Q (128 rows x 8 units)
    {
        const __half* qg = qkv + ((size_t)(b * T_SEQ + qi * 128)) * QKV_LD + h * 64;
        #pragma unroll
        for (int t = 0; t < 4; t++) {
            int idx = t * 256 + tid;
            int r = idx >> 3, u = idx & 7;
            cp_async16(Qu + (uint32_t)(r * 64 + ((u ^ (r & 7)) << 3)) * 2,
                       qg + (size_t)r * QKV_LD + u * 8);
        }
    }
    auto loadKV = [&](int kt, int bb) {
        const __half* kg = qkv + ((size_t)(b * T_SEQ + kt * 64)) * QKV_LD + C_DIM + h * 64;
        const __half* vg = kg + C_DIM;
        uint32_t kb = Ku + (uint32_t)(bb * 4096) * 2;
        uint32_t vb = Vu + (uint32_t)(bb * 4096) * 2;
        #pragma unroll
        for (int t = 0; t < 2; t++) {
            int idx = t * 256 + tid;
            int r = idx >> 3, u = idx & 7;
            uint32_t so = (uint32_t)(r * 64 + ((u ^ (r & 7)) << 3)) * 2;
            cp_async16(kb + so, kg + (size_t)r * QKV_LD + u * 8);
            cp_async16(vb + so, vg + (size_t)r * QKV_LD + u * 8);
        }
    };
    loadKV(0, 0); CP_COMMIT();

    int nkt = 2 * qi + 2;
    uint32_t qf[4][4];
    float oacc[8][4];
    #pragma unroll
    for (int i = 0; i < 8; i++)
        #pragma unroll
        for (int q = 0; q < 4; q++) oacc[i][q] = 0.f;

    int qg0 = qi * 128 + qrow0 + g;
    int qg1 = qg0 + 8;
    float q2a = 0.f, q2b = 0.f;

    for (int kt = 0; kt < nkt; kt++) {
        int buf = kt & 1;
        if (kt + 1 < nkt) { loadKV(kt + 1, buf ^ 1); CP_COMMIT(); CP_WAIT(1); }
        else              { CP_WAIT(0); }
        __syncthreads();

        if (kt == 0 && tid < 128) {        // q2
            int r = tid;
            float s = 0.f;
            #pragma unroll
            for (int u = 0; u < 8; u++) {
                uint4 v = *(const uint4*)(Qs + r * 64 + ((u ^ (r & 7)) << 3));
                const uint32_t* w = &v.x;
                #pragma unroll
                for (int j = 0; j < 4; j++) {
                    float2 f = __half22float2(*(const __half2*)&w[j]);
                    s += f.x * f.x + f.y * f.y;
                }
            }
            q2s[r] = s;
        }
        if (tid >= 128 && tid < 192) {     // k2 for this buffer
            int r = tid - 128;
            const __half* kb = Ks + buf * 4096;
            float s = 0.f;
            #pragma unroll
            for (int u = 0; u < 8; u++) {
                uint4 v = *(const uint4*)(kb + r * 64 + ((u ^ (r & 7)) << 3));
                const uint32_t* w = &v.x;
                #pragma unroll
                for (int j = 0; j < 4; j++) {
                    float2 f = __half22float2(*(const __half2*)&w[j]);
                    s += f.x * f.x + f.y * f.y;
                }
            }
            k2s[buf * 64 + r] = s;
        }
        __syncthreads();

        if (kt == 0) {
            #pragma unroll
            for (int ks = 0; ks < 4; ks++) {
                int m = lane >> 3;
                int r = qrow0 + ((m & 1) << 3) + (lane & 7);
                int d0 = ks * 16 + ((m >> 1) << 3);
                LDMX4(qf[ks], Qu + (uint32_t)haddr(r, d0) * 2);
            }
            q2a = q2s[qrow0 + g];
            q2b = q2s[qrow0 + g + 8];
        }

        uint32_t kbase = Ku + (uint32_t)(buf * 4096) * 2;
        uint32_t vbase = Vu + (uint32_t)(buf * 4096) * 2;

        // ---- S = Q @ K^T ----
        float sacc[8][4];
        #pragma unroll
        for (int i = 0; i < 8; i++)
            #pragma unroll
            for (int q = 0; q < 4; q++) sacc[i][q] = 0.f;
        #pragma unroll
        for (int ks = 0; ks < 4; ks++) {
            uint32_t kf[4][4];
            #pragma unroll
            for (int nt2 = 0; nt2 < 4; nt2++) {
                int m = lane >> 3;
                int tok = nt2 * 16 + ((m >> 1) << 3) + (lane & 7);
                int d0 = ks * 16 + ((m & 1) << 3);
                LDMX4(kf[nt2], kbase + (uint32_t)haddr(tok, d0) * 2);
            }
            #pragma unroll
            for (int nt2 = 0; nt2 < 4; nt2++) {
                mma_f16(sacc[2 * nt2],     qf[ks], &kf[nt2][0]);
                mma_f16(sacc[2 * nt2 + 1], qf[ks], &kf[nt2][2]);
            }
        }

        // ---- scores -> P (fp16 in registers) ----
        uint32_t ph[8], ph2[8];
        int kc0 = kt * 64 + 2 * t4;
        #pragma unroll
        for (int nt = 0; nt < 8; nt++) {
            int c0 = kc0 + nt * 8;
            float k2a = k2s[buf * 64 + nt * 8 + 2 * t4];
            float k2b = k2s[buf * 64 + nt * 8 + 2 * t4 + 1];
            float e00 = (c0     <= qg0) ? __expf(scale * (q2a + k2a - 2.f * sacc[nt][0])) : 0.f;
            float e01 = (c0 + 1 <= qg0) ? __expf(scale * (q2a + k2b - 2.f * sacc[nt][1])) : 0.f;
            float e10 = (c0     <= qg1) ? __expf(scale * (q2b + k2a - 2.f * sacc[nt][2])) : 0.f;
            float e11 = (c0 + 1 <= qg1) ? __expf(scale * (q2b + k2b - 2.f * sacc[nt][3])) : 0.f;
            __half2 p0 = __floats2half2_rn(e00, e01);
            __half2 p1 = __floats2half2_rn(e10, e11);
            ph[nt]  = *(uint32_t*)&p0;
            ph2[nt] = *(uint32_t*)&p1;
        }

        // ---- O += P @ V ----
        #pragma unroll
        for (int kc = 0; kc < 4; kc++) {
            uint32_t vf[4][4];
            #pragma unroll
            for (int dn2 = 0; dn2 < 4; dn2++) {
                int m = lane >> 3;
                int tok = kc * 16 + ((m & 1) << 3) + (lane & 7);
                int d0 = dn2 * 16 + ((m >> 1) << 3);
                LDMX4T(vf[dn2], vbase + (uint32_t)haddr(tok, d0) * 2);
            }
            uint32_t a[4] = { ph[2 * kc], ph2[2 * kc], ph[2 * kc + 1], ph2[2 * kc + 1] };
            #pragma unroll
            for (int dn2 = 0; dn2 < 4; dn2++) {
                mma_f16(oacc[2 * dn2],     a, &vf[dn2][0]);
                mma_f16(oacc[2 * dn2 + 1], a, &vf[dn2][2]);
            }
        }
        __syncthreads();
    }

    // ---- write y (fp16, perm16) ----
    size_t row0 = (size_t)(b * T_SEQ + qi * 128 + qrow0 + g);
    #pragma unroll
    for (int dn = 0; dn < 8; dn++) {
        int col = h * 64 + dn * 8 + 2 * t4;
        int pc = perm16(col);
        __half2 v0 = __floats2half2_rn(oacc[dn][0], oacc[dn][1]);
        __half2 v1 = __floats2half2_rn(oacc[dn][2], oacc[dn][3]);
        *(__half2*)(y + row0 * C_DIM + pc)       = v0;
        *(__half2*)(y + (row0 + 8) * C_DIM + pc) = v1;
    }
}

// ---------------- launch ------------------------------------------------------
extern "C" void kernel_launch(void* const* d_in, const int* in_sizes, int n_in,
                              void* d_out, int out_size) {
    const float* x           = (const float*)d_in[0];
    const float* w_ln1       = (const float*)d_in[1];
    const float* w_attn      = (const float*)d_in[2];
    const float* w_attn_proj = (const float*)d_in[3];
    const float* w_ln2       = (const float*)d_in[4];
    const float* w_fc        = (const float*)d_in[5];
    const float* w_mlp_proj  = (const float*)d_in[6];
    float* out = (float*)d_out;

    __half *xn, *qkv, *y, *hbuf, *wattnT, *wprojT, *wfcT, *wmlpT;
    float *x2;
    cudaGetSymbolAddress((void**)&xn,     g_xn);
    cudaGetSymbolAddress((void**)&qkv,    g_qkv);
    cudaGetSymbolAddress((void**)&y,      g_y);
    cudaGetSymbolAddress((void**)&x2,     g_x2);
    cudaGetSymbolAddress((void**)&hbuf,   g_h);
    cudaGetSymbolAddress((void**)&wattnT, g_wattnT);
    cudaGetSymbolAddress((void**)&wprojT, g_wprojT);
    cudaGetSymbolAddress((void**)&wfcT,   g_wfcT);
    cudaGetSymbolAddress((void**)&wmlpT,  g_wmlpT);

    cudaFuncSetAttribute(attn_kernel, cudaFuncAttributeMaxDynamicSharedMemorySize, ATTN_SMEM_BYTES);
    cudaFuncSetAttribute(mma_gemm_kernel<0>, cudaFuncAttributeMaxDynamicSharedMemorySize, GEMM_SMEM_BYTES);
    cudaFuncSetAttribute(mma_gemm_kernel<1>, cudaFuncAttributeMaxDynamicSharedMemorySize, GEMM_SMEM_BYTES);
    cudaFuncSetAttribute(mma_gemm_kernel<2>, cudaFuncAttributeMaxDynamicSharedMemorySize, GEMM_SMEM_BYTES);

    // 0. all weight transposes, one launch
    transpose_all_kernel<<<SEG3, 256>>>(w_attn, wattnT, w_attn_proj, wprojT,
                                        w_fc, wfcT, w_mlp_proj, wmlpT);
    // 1. ln1(x) -> xn  (fp16, k-permuted)
    ln_kernel<<<M_ROWS, 256>>>(x, w_ln1, xn);
    // 2. qkv = xn @ w_attn  (fp16 natural out)
    mma_gemm_kernel<0><<<dim3(QKV_LD / 256, M_ROWS / 128), 256, GEMM_SMEM_BYTES>>>(
        xn, wattnT, nullptr, qkv, M_ROWS, QKV_LD, C_DIM);
    // 3. attention -> y (fp16, k-permuted)
    attn_kernel<<<dim3(T_SEQ / 128, H_HEADS, 2), 256, ATTN_SMEM_BYTES>>>(qkv, y);
    // 4. x2 = y @ w_attn_proj + x  (f32 out)
    mma_gemm_kernel<1><<<dim3(C_DIM / 256, M_ROWS / 128), 256, GEMM_SMEM_BYTES>>>(
        y, wprojT, x, x2, M_ROWS, C_DIM, C_DIM);
    // 5. ln2(x2) -> xn
    ln_kernel<<<M_ROWS, 256>>>(x2, w_ln2, xn);
    // 6. h = gelu(xn @ w_fc)  (fp16, k-permuted)
    mma_gemm_kernel<2><<<dim3(FC_DIM / 256, M_ROWS / 128), 256, GEMM_SMEM_BYTES>>>(
        xn, wfcT, nullptr, hbuf, M_ROWS, FC_DIM, C_DIM);
    // 7. out = h @ w_mlp_proj + x2  (f32 out)
    mma_gemm_kernel<1><<<dim3(C_DIM / 256, M_ROWS / 128), 256, GEMM_SMEM_BYTES>>>(
        hbuf, wmlpT, x2, out, M_ROWS, C_DIM, FC_DIM);
}

// round 9
// speedup vs baseline: 3.2987x; 1.0394x over previous
#include <cuda_runtime.h>
#include <cuda_fp16.h>
#include <math.h>
#include <cstdint>

// Problem: B=2, T=2048, C=768, H=12, D=64.  M = B*T = 4096 rows.
#define M_ROWS 4096
#define C_DIM  768
#define T_SEQ  2048
#define H_HEADS 12
#define D_HEAD 64
#define QKV_LD (3*C_DIM)   // 2304
#define FC_DIM (4*C_DIM)   // 3072

// ---------------- scratch (device globals: no allocation allowed) -------------
__device__ __half g_xn [M_ROWS * C_DIM];
__device__ __half g_qkv[M_ROWS * QKV_LD];   // fp16 natural layout
__device__ __half g_y  [M_ROWS * C_DIM];    // attention partial 0 -> merged y
__device__ __half g_y2 [M_ROWS * C_DIM];    // attention partial 1
__device__ float  g_x2 [M_ROWS * C_DIM];
__device__ __half g_h  [M_ROWS * FC_DIM];
// transposed (K-major, fp16, k-permuted) weights
__device__ __half g_wattnT[QKV_LD * C_DIM];
__device__ __half g_wprojT[C_DIM * C_DIM];
__device__ __half g_wfcT  [FC_DIM * C_DIM];
__device__ __half g_wmlpT [C_DIM * FC_DIM];

// ======================= helpers ==============================================
__device__ __forceinline__ uint32_t smem_u32(const void* p) {
    uint32_t a;
    asm("{ .reg .u64 t; cvta.to.shared.u64 t, %1; cvt.u32.u64 %0, t; }" : "=r"(a) : "l"(p));
    return a;
}
__device__ __forceinline__ void cp_async16(uint32_t s, const void* g) {
    asm volatile("cp.async.cg.shared.global [%0], [%1], 16;" :: "r"(s), "l"(g));
}
#define CP_COMMIT() asm volatile("cp.async.commit_group;" ::: "memory")
#define CP_WAIT(n)  asm volatile("cp.async.wait_group %0;" :: "n"(n) : "memory")

// permute k within 16-groups: a thread's mma fragment halves
// {2t4, 2t4+1, 2t4+8, 2t4+9} become 4 contiguous halves at 16g + 4*t4.
__device__ __forceinline__ int perm16(int k) {
    int lo = k & 15;
    int p = ((lo & 7) >> 1) * 4 + ((lo >> 3) << 1) + (lo & 1);
    return (k & ~15) | p;
}
// smem half-index for tile row r, half col k; 16B-unit XOR swizzle
__device__ __forceinline__ int haddr(int r, int k) {
    int u = k >> 3;
    return r * 64 + (((u ^ (r & 7)) << 3) | (k & 7));
}
// D(16x8,f32) += A(16x16,f16) * B(16x8,f16)
__device__ __forceinline__ void mma_f16(float* d, const uint32_t* a, const uint32_t* b) {
    asm volatile(
        "mma.sync.aligned.m16n8k16.row.col.f32.f16.f16.f32 "
        "{%0,%1,%2,%3}, {%4,%5,%6,%7}, {%8,%9}, {%0,%1,%2,%3};"
        : "+f"(d[0]), "+f"(d[1]), "+f"(d[2]), "+f"(d[3])
        : "r"(a[0]), "r"(a[1]), "r"(a[2]), "r"(a[3]), "r"(b[0]), "r"(b[1]));
}
#define LDMX4(r, addr) \
    asm volatile("ldmatrix.sync.aligned.m8n8.x4.shared.b16 {%0,%1,%2,%3}, [%4];" \
        : "=r"((r)[0]), "=r"((r)[1]), "=r"((r)[2]), "=r"((r)[3]) : "r"(addr))
#define LDMX4T(r, addr) \
    asm volatile("ldmatrix.sync.aligned.m8n8.x4.trans.shared.b16 {%0,%1,%2,%3}, [%4];" \
        : "=r"((r)[0]), "=r"((r)[1]), "=r"((r)[2]), "=r"((r)[3]) : "r"(addr))

// ---------------- LayerNorm (output: fp16, k-permuted) ------------------------
__global__ __launch_bounds__(256) void ln_kernel(const float* __restrict__ x,
                                                 const float* __restrict__ w,
                                                 __half* __restrict__ out) {
    int row = blockIdx.x;
    const float* xr = x + (size_t)row * C_DIM;
    float s = 0.f, s2 = 0.f;
    for (int i = threadIdx.x; i < C_DIM; i += 256) {
        float v = xr[i];
        s += v; s2 += v * v;
    }
    #pragma unroll
    for (int o = 16; o; o >>= 1) {
        s  += __shfl_xor_sync(0xFFFFFFFFu, s,  o);
        s2 += __shfl_xor_sync(0xFFFFFFFFu, s2, o);
    }
    __shared__ float ss[8], ss2[8];
    int wid = threadIdx.x >> 5, lid = threadIdx.x & 31;
    if (lid == 0) { ss[wid] = s; ss2[wid] = s2; }
    __syncthreads();
    if (wid == 0) {
        s  = (lid < 8) ? ss[lid]  : 0.f;
        s2 = (lid < 8) ? ss2[lid] : 0.f;
        #pragma unroll
        for (int o = 4; o; o >>= 1) {
            s  += __shfl_xor_sync(0xFFFFFFFFu, s,  o);
            s2 += __shfl_xor_sync(0xFFFFFFFFu, s2, o);
        }
        if (lid == 0) { ss[0] = s; ss2[0] = s2; }
    }
    __syncthreads();
    float mean = ss[0] * (1.f / C_DIM);
    float var  = ss2[0] * (1.f / C_DIM) - mean * mean;
    float inv  = rsqrtf(var + 1e-5f);
    for (int i = threadIdx.x; i < C_DIM; i += 256)
        out[(size_t)row * C_DIM + perm16(i)] = __float2half((xr[i] - mean) * inv * w[i]);
}

// ---------------- All 4 weight transposes in one launch ------------------------
#define SEG0 1728
#define SEG1 (SEG0 + 576)
#define SEG2 (SEG1 + 2304)
#define SEG3 (SEG2 + 2304)    // 6912 total

__global__ __launch_bounds__(256) void transpose_all_kernel(
    const float* __restrict__ in0, __half* __restrict__ out0,
    const float* __restrict__ in1, __half* __restrict__ out1,
    const float* __restrict__ in2, __half* __restrict__ out2,
    const float* __restrict__ in3, __half* __restrict__ out3)
{
    int bid = blockIdx.x;
    const float* in; __half* out; int rows, cols, t0, ntx;
    if (bid < SEG0)      { in = in0; out = out0; rows = C_DIM;  cols = QKV_LD; t0 = 0;    ntx = QKV_LD / 32; }
    else if (bid < SEG1) { in = in1; out = out1; rows = C_DIM;  cols = C_DIM;  t0 = SEG0; ntx = C_DIM / 32; }
    else if (bid < SEG2) { in = in2; out = out2; rows = C_DIM;  cols = FC_DIM; t0 = SEG1; ntx = FC_DIM / 32; }
    else                 { in = in3; out = out3; rows = FC_DIM; cols = C_DIM;  t0 = SEG2; ntx = C_DIM / 32; }
    int t = bid - t0;
    int bx = (t % ntx) * 32;
    int by = (t / ntx) * 32;

    __shared__ float tile[32][33];
    int tx = threadIdx.x & 31, ty = threadIdx.x >> 5;
    int x = bx + tx;
    #pragma unroll
    for (int j = 0; j < 32; j += 8)
        tile[ty + j][tx] = in[(size_t)(by + ty + j) * cols + x];
    __syncthreads();
    int ox = by + tx;
    #pragma unroll
    for (int j = 0; j < 32; j += 8) {
        float v = tile[tx][ty + j];
        out[(size_t)(bx + ty + j) * rows + perm16(ox)] = __float2half(v);
    }
}

// ---------------- fp16 mma GEMM, 128x256 CTA tile, warp tile 64x64 ------------
// MODE 0: C = A@B -> fp16 natural ; MODE 1: C = A@B + R -> f32 ;
// MODE 2: C = gelu(A@B) -> fp16, k-permuted
#define STAGE_H 24576                        // (128 + 256) * 64 halves
#define GEMM_SMEM_BYTES (3 * STAGE_H * 2)    // 147456

template<int MODE>
__global__ __launch_bounds__(256, 1) void mma_gemm_kernel(
    const __half* __restrict__ A, const __half* __restrict__ BT,
    const float* __restrict__ R, void* __restrict__ Cv,
    int M, int N, int K)
{
    extern __shared__ __half smh[];
    uint32_t sm_u = smem_u32(smh);

    int tid  = threadIdx.x;
    int wid  = tid >> 5, lane = tid & 31;
    int wm   = wid & 1;
    int wn   = wid >> 1;
    int g    = lane >> 2, t4 = lane & 3;
    int m0 = blockIdx.y * 128, n0 = blockIdx.x * 256;

    float acc[4][8][4];
    #pragma unroll
    for (int i = 0; i < 4; i++)
        #pragma unroll
        for (int j = 0; j < 8; j++)
            #pragma unroll
            for (int q = 0; q < 4; q++) acc[i][j][q] = 0.f;

    const int nch = K >> 6;

    auto issue = [&](int k0, int s) {
        uint32_t sb = sm_u + (uint32_t)(s * STAGE_H) * 2;
        #pragma unroll
        for (int t = 0; t < 4; t++) {
            int idx = t * 256 + tid;
            int row = idx >> 3, u = idx & 7;
            cp_async16(sb + (uint32_t)(row * 64 + ((u ^ (row & 7)) << 3)) * 2,
                       A + (size_t)(m0 + row) * K + k0 + u * 8);
        }
        uint32_t bb = sb + 8192u * 2;
        #pragma unroll
        for (int t = 0; t < 8; t++) {
            int idx = t * 256 + tid;
            int row = idx >> 3, u = idx & 7;
            cp_async16(bb + (uint32_t)(row * 64 + ((u ^ (row & 7)) << 3)) * 2,
                       BT + (size_t)(n0 + row) * K + k0 + u * 8);
        }
    };

    issue(0, 0); CP_COMMIT();
    if (nch > 1) { issue(64, 1); CP_COMMIT(); }

    for (int ic = 0; ic < nch; ic++) {
        if (ic + 1 < nch) CP_WAIT(1);
        else              CP_WAIT(0);
        __syncthreads();
        if (ic + 2 < nch) { issue((ic + 2) * 64, (ic + 2) % 3); CP_COMMIT(); }

        const __half* Ah = smh + (ic % 3) * STAGE_H;
        const __half* Bh = Ah + 8192;
        #pragma unroll
        for (int ks = 0; ks < 4; ks++) {
            uint32_t a[4][4], b[8][2];
            int kc = ks * 16 + 4 * t4;
            #pragma unroll
            for (int mt = 0; mt < 4; mt++) {
                int r = wm * 64 + mt * 16 + g;
                uint2 lo = *(const uint2*)(Ah + haddr(r,     kc));
                uint2 hi = *(const uint2*)(Ah + haddr(r + 8, kc));
                a[mt][0] = lo.x; a[mt][2] = lo.y;
                a[mt][1] = hi.x; a[mt][3] = hi.y;
            }
            #pragma unroll
            for (int nt = 0; nt < 8; nt++) {
                int nr = wn * 64 + nt * 8 + g;
                uint2 bv = *(const uint2*)(Bh + haddr(nr, kc));
                b[nt][0] = bv.x; b[nt][1] = bv.y;
            }
            #pragma unroll
            for (int mt = 0; mt < 4; mt++)
                #pragma unroll
                for (int nt = 0; nt < 8; nt++)
                    mma_f16(acc[mt][nt], a[mt], b[nt]);
        }
    }

    #pragma unroll
    for (int mt = 0; mt < 4; mt++) {
        int r0 = m0 + wm * 64 + mt * 16 + g;
        #pragma unroll
        for (int nt = 0; nt < 8; nt++) {
            int c = n0 + wn * 64 + nt * 8 + 2 * t4;
            #pragma unroll
            for (int half_ = 0; half_ < 2; half_++) {
                int r = r0 + half_ * 8;
                float v0 = acc[mt][nt][half_ * 2 + 0];
                float v1 = acc[mt][nt][half_ * 2 + 1];
                if (MODE == 1) {
                    float* C = (float*)Cv;
                    float2 rv = *(const float2*)(R + (size_t)r * N + c);
                    v0 += rv.x; v1 += rv.y;
                    *(float2*)(C + (size_t)r * N + c) = make_float2(v0, v1);
                } else if (MODE == 2) {
                    __half* C = (__half*)Cv;
                    v0 = 0.5f * v0 * (1.0f + erff(v0 * 0.70710678118654752f));
                    v1 = 0.5f * v1 * (1.0f + erff(v1 * 0.70710678118654752f));
                    C[(size_t)r * N + perm16(c)]     = __float2half(v0);
                    C[(size_t)r * N + perm16(c + 1)] = __float2half(v1);
                } else {
                    __half* C = (__half*)Cv;
                    *(__half2*)(C + (size_t)r * N + c) = __floats2half2_rn(v0, v1);
                }
            }
        }
    }
}

// ---------------- Attention: fp16 mma, 128q blocks, split-K (2 CTAs/block) ----
// scores = exp(-(q2+k2-2qk)/(2 sqrt(D))), causal, unnormalized (pure sum ->
// split-K partials just add). Split s handles K-tiles [s*(qi+1), (s+1)*(qi+1)).
#define ATTN_SMEM_BYTES (24576 * 2 + 256 * 4)

__global__ __launch_bounds__(256, 2) void attn_kernel(const __half* __restrict__ qkv,
                                                      __half* __restrict__ y0,
                                                      __half* __restrict__ y1) {
    int qi = gridDim.x - 1 - blockIdx.x;   // big blocks first
    int h = blockIdx.y;
    int b = blockIdx.z & 1;
    int sp = blockIdx.z >> 1;              // split index 0/1
    int kt0 = sp * (qi + 1);
    int kt1 = kt0 + qi + 1;
    __half* yb = sp ? y1 : y0;

    extern __shared__ __half smh[];
    __half* Qs = smh;                 // 128 x 64
    __half* Ks = smh + 8192;          // 2 x 64 x 64
    __half* Vs = smh + 16384;         // 2 x 64 x 64
    float* q2s = (float*)(smh + 24576);   // 128
    float* k2s = q2s + 128;               // 2 x 64
    uint32_t Qu = smem_u32(Qs), Ku = smem_u32(Ks), Vu = smem_u32(Vs);

    int tid = threadIdx.x, wid = tid >> 5, lane = tid & 31;
    int g = lane >> 2, t4 = lane & 3;
    int qrow0 = wid * 16;
    const float scale = -0.0625f;     // -1/(2*sqrt(64))

    // load Q (128 rows x 8 units)
    {
        const __half* qg = qkv + ((size_t)(b * T_SEQ + qi * 128)) * QKV_LD + h * 64;
        #pragma unroll
        for (int t = 0; t < 4; t++) {
            int idx = t * 256 + tid;
            int r = idx >> 3, u = idx & 7;
            cp_async16(Qu + (uint32_t)(r * 64 + ((u ^ (r & 7)) << 3)) * 2,
                       qg + (size_t)r * QKV_LD + u * 8);
        }
    }
    auto loadKV = [&](int kt, int bb) {
        const __half* kg = qkv + ((size_t)(b * T_SEQ + kt * 64)) * QKV_LD + C_DIM + h * 64;
        const __half* vg = kg + C_DIM;
        uint32_t kb = Ku + (uint32_t)(bb * 4096) * 2;
        uint32_t vb = Vu + (uint32_t)(bb * 4096) * 2;
        #pragma unroll
        for (int t = 0; t < 2; t++) {
            int idx = t * 256 + tid;
            int r = idx >> 3, u = idx & 7;
            uint32_t so = (uint32_t)(r * 64 + ((u ^ (r & 7)) << 3)) * 2;
            cp_async16(kb + so, kg + (size_t)r * QKV_LD + u * 8);
            cp_async16(vb + so, vg + (size_t)r * QKV_LD + u * 8);
        }
    };
    loadKV(kt0, 0); CP_COMMIT();

    uint32_t qf[4][4];
    float oacc[8][4];
    #pragma unroll
    for (int i = 0; i < 8; i++)
        #pragma unroll
        for (int q = 0; q < 4; q++) oacc[i][q] = 0.f;

    int qg0 = qi * 128 + qrow0 + g;
    int qg1 = qg0 + 8;
    float q2a = 0.f, q2b = 0.f;

    for (int kt = kt0; kt < kt1; kt++) {
        int buf = (kt - kt0) & 1;
        if (kt + 1 < kt1) { loadKV(kt + 1, buf ^ 1); CP_COMMIT(); CP_WAIT(1); }
        else              { CP_WAIT(0); }
        __syncthreads();

        if (kt == kt0 && tid < 128) {      // q2
            int r = tid;
            float s = 0.f;
            #pragma unroll
            for (int u = 0; u < 8; u++) {
                uint4 v = *(const uint4*)(Qs + r * 64 + ((u ^ (r & 7)) << 3));
                const uint32_t* w = &v.x;
                #pragma unroll
                for (int j = 0; j < 4; j++) {
                    float2 f = __half22float2(*(const __half2*)&w[j]);
                    s += f.x * f.x + f.y * f.y;
                }
            }
            q2s[r] = s;
        }
        if (tid >= 128 && tid < 192) {     // k2 for this buffer
            int r = tid - 128;
            const __half* kb = Ks + buf * 4096;
            float s = 0.f;
            #pragma unroll
            for (int u = 0; u < 8; u++) {
                uint4 v = *(const uint4*)(kb + r * 64 + ((u ^ (r & 7)) << 3));
                const uint32_t* w = &v.x;
                #pragma unroll
                for (int j = 0; j < 4; j++) {
                    float2 f = __half22float2(*(const __half2*)&w[j]);
                    s += f.x * f.x + f.y * f.y;
                }
            }
            k2s[buf * 64 + r] = s;
        }
        __syncthreads();

        if (kt == kt0) {
            #pragma unroll
            for (int ks = 0; ks < 4; ks++) {
                int m = lane >> 3;
                int r = qrow0 + ((m & 1) << 3) + (lane & 7);
                int d0 = ks * 16 + ((m >> 1) << 3);
                LDMX4(qf[ks], Qu + (uint32_t)haddr(r, d0) * 2);
            }
            q2a = q2s[qrow0 + g];
            q2b = q2s[qrow0 + g + 8];
        }

        uint32_t kbase = Ku + (uint32_t)(buf * 4096) * 2;
        uint32_t vbase = Vu + (uint32_t)(buf * 4096) * 2;

        // ---- S = Q @ K^T ----
        float sacc[8][4];
        #pragma unroll
        for (int i = 0; i < 8; i++)
            #pragma unroll
            for (int q = 0; q < 4; q++) sacc[i][q] = 0.f;
        #pragma unroll
        for (int ks = 0; ks < 4; ks++) {
            uint32_t kf[4][4];
            #pragma unroll
            for (int nt2 = 0; nt2 < 4; nt2++) {
                int m = lane >> 3;
                int tok = nt2 * 16 + ((m >> 1) << 3) + (lane & 7);
                int d0 = ks * 16 + ((m & 1) << 3);
                LDMX4(kf[nt2], kbase + (uint32_t)haddr(tok, d0) * 2);
            }
            #pragma unroll
            for (int nt2 = 0; nt2 < 4; nt2++) {
                mma_f16(sacc[2 * nt2],     qf[ks], &kf[nt2][0]);
                mma_f16(sacc[2 * nt2 + 1], qf[ks], &kf[nt2][2]);
            }
        }

        // ---- scores -> P (fp16 in registers) ----
        uint32_t ph[8], ph2[8];
        int kc0 = kt * 64 + 2 * t4;
        #pragma unroll
        for (int nt = 0; nt < 8; nt++) {
            int c0 = kc0 + nt * 8;
            float k2a = k2s[buf * 64 + nt * 8 + 2 * t4];
            float k2b = k2s[buf * 64 + nt * 8 + 2 * t4 + 1];
            float e00 = (c0     <= qg0) ? __expf(scale * (q2a + k2a - 2.f * sacc[nt][0])) : 0.f;
            float e01 = (c0 + 1 <= qg0) ? __expf(scale * (q2a + k2b - 2.f * sacc[nt][1])) : 0.f;
            float e10 = (c0     <= qg1) ? __expf(scale * (q2b + k2a - 2.f * sacc[nt][2])) : 0.f;
            float e11 = (c0 + 1 <= qg1) ? __expf(scale * (q2b + k2b - 2.f * sacc[nt][3])) : 0.f;
            __half2 p0 = __floats2half2_rn(e00, e01);
            __half2 p1 = __floats2half2_rn(e10, e11);
            ph[nt]  = *(uint32_t*)&p0;
            ph2[nt] = *(uint32_t*)&p1;
        }

        // ---- O += P @ V ----
        #pragma unroll
        for (int kc = 0; kc < 4; kc++) {
            uint32_t vf[4][4];
            #pragma unroll
            for (int dn2 = 0; dn2 < 4; dn2++) {
                int m = lane >> 3;
                int tok = kc * 16 + ((m & 1) << 3) + (lane & 7);
                int d0 = dn2 * 16 + ((m >> 1) << 3);
                LDMX4T(vf[dn2], vbase + (uint32_t)haddr(tok, d0) * 2);
            }
            uint32_t a[4] = { ph[2 * kc], ph2[2 * kc], ph[2 * kc + 1], ph2[2 * kc + 1] };
            #pragma unroll
            for (int dn2 = 0; dn2 < 4; dn2++) {
                mma_f16(oacc[2 * dn2],     a, &vf[dn2][0]);
                mma_f16(oacc[2 * dn2 + 1], a, &vf[dn2][2]);
            }
        }
        __syncthreads();
    }

    // ---- write partial y (fp16, perm16) ----
    size_t row0 = (size_t)(b * T_SEQ + qi * 128 + qrow0 + g);
    #pragma unroll
    for (int dn = 0; dn < 8; dn++) {
        int col = h * 64 + dn * 8 + 2 * t4;
        int pc = perm16(col);
        __half2 v0 = __floats2half2_rn(oacc[dn][0], oacc[dn][1]);
        __half2 v1 = __floats2half2_rn(oacc[dn][2], oacc[dn][3]);
        *(__half2*)(yb + row0 * C_DIM + pc)       = v0;
        *(__half2*)(yb + (row0 + 8) * C_DIM + pc) = v1;
    }
}

// ---------------- merge split-K partials: y = y0 + y1 (in place on y0) --------
__global__ __launch_bounds__(256) void merge_y_kernel(__half2* __restrict__ y0,
                                                      const __half2* __restrict__ y1) {
    const int n2 = M_ROWS * C_DIM / 2;
    int i = blockIdx.x * 256 + threadIdx.x;
    int stride = gridDim.x * 256;
    for (; i < n2; i += stride)
        y0[i] = __hadd2(y0[i], y1[i]);
}

// ---------------- launch ------------------------------------------------------
extern "C" void kernel_launch(void* const* d_in, const int* in_sizes, int n_in,
                              void* d_out, int out_size) {
    const float* x           = (const float*)d_in[0];
    const float* w_ln1       = (const float*)d_in[1];
    const float* w_attn      = (const float*)d_in[2];
    const float* w_attn_proj = (const float*)d_in[3];
    const float* w_ln2       = (const float*)d_in[4];
    const float* w_fc        = (const float*)d_in[5];
    const float* w_mlp_proj  = (const float*)d_in[6];
    float* out = (float*)d_out;

    __half *xn, *qkv, *y, *y2, *hbuf, *wattnT, *wprojT, *wfcT, *wmlpT;
    float *x2;
    cudaGetSymbolAddress((void**)&xn,     g_xn);
    cudaGetSymbolAddress((void**)&qkv,    g_qkv);
    cudaGetSymbolAddress((void**)&y,      g_y);
    cudaGetSymbolAddress((void**)&y2,     g_y2);
    cudaGetSymbolAddress((void**)&x2,     g_x2);
    cudaGetSymbolAddress((void**)&hbuf,   g_h);
    cudaGetSymbolAddress((void**)&wattnT, g_wattnT);
    cudaGetSymbolAddress((void**)&wprojT, g_wprojT);
    cudaGetSymbolAddress((void**)&wfcT,   g_wfcT);
    cudaGetSymbolAddress((void**)&wmlpT,  g_wmlpT);

    cudaFuncSetAttribute(attn_kernel, cudaFuncAttributeMaxDynamicSharedMemorySize, ATTN_SMEM_BYTES);
    cudaFuncSetAttribute(mma_gemm_kernel<0>, cudaFuncAttributeMaxDynamicSharedMemorySize, GEMM_SMEM_BYTES);
    cudaFuncSetAttribute(mma_gemm_kernel<1>, cudaFuncAttributeMaxDynamicSharedMemorySize, GEMM_SMEM_BYTES);
    cudaFuncSetAttribute(mma_gemm_kernel<2>, cudaFuncAttributeMaxDynamicSharedMemorySize, GEMM_SMEM_BYTES);

    // 0. all weight transposes, one launch
    transpose_all_kernel<<<SEG3, 256>>>(w_attn, wattnT, w_attn_proj, wprojT,
                                        w_fc, wfcT, w_mlp_proj, wmlpT);
    // 1. ln1(x) -> xn  (fp16, k-permuted)
    ln_kernel<<<M_ROWS, 256>>>(x, w_ln1, xn);
    // 2. qkv = xn @ w_attn  (fp16 natural out)
    mma_gemm_kernel<0><<<dim3(QKV_LD / 256, M_ROWS / 128), 256, GEMM_SMEM_BYTES>>>(
        xn, wattnT, nullptr, qkv, M_ROWS, QKV_LD, C_DIM);
    // 3. attention, 2-way split-K -> y (partial 0), y2 (partial 1)
    attn_kernel<<<dim3(T_SEQ / 128, H_HEADS, 4), 256, ATTN_SMEM_BYTES>>>(qkv, y, y2);
    // 3b. y += y2
    merge_y_kernel<<<1184, 256>>>((__half2*)y, (const __half2*)y2);
    // 4. x2 = y @ w_attn_proj + x  (f32 out)
    mma_gemm_kernel<1><<<dim3(C_DIM / 256, M_ROWS / 128), 256, GEMM_SMEM_BYTES>>>(
        y, wprojT, x, x2, M_ROWS, C_DIM, C_DIM);
    // 5. ln2(x2) -> xn
    ln_kernel<<<M_ROWS, 256>>>(x2, w_ln2, xn);
    // 6. h = gelu(xn @ w_fc)  (fp16, k-permuted)
    mma_gemm_kernel<2><<<dim3(FC_DIM / 256, M_ROWS / 128), 256, GEMM_SMEM_BYTES>>>(
        xn, wfcT, nullptr, hbuf, M_ROWS, FC_DIM, C_DIM);
    // 7. out = h @ w_mlp_proj + x2  (f32 out)
    mma_gemm_kernel<1><<<dim3(C_DIM / 256, M_ROWS / 128), 256, GEMM_SMEM_BYTES>>>(
        hbuf, wmlpT, x2, out, M_ROWS, C_DIM, FC_DIM);
}

// round 10
// speedup vs baseline: 3.6636x; 1.1106x over previous
#include <cuda_runtime.h>
#include <cuda_fp16.h>
#include <math.h>
#include <cstdint>

// Problem: B=2, T=2048, C=768, H=12, D=64.  M = B*T = 4096 rows.
#define M_ROWS 4096
#define C_DIM  768
#define T_SEQ  2048
#define H_HEADS 12
#define D_HEAD 64
#define QKV_LD (3*C_DIM)   // 2304
#define FC_DIM (4*C_DIM)   // 3072

// ---------------- scratch (device globals: no allocation allowed) -------------
__device__ __half g_xn [M_ROWS * C_DIM];
__device__ __half g_qkv[M_ROWS * QKV_LD];   // fp16 natural layout
__device__ __half g_y  [M_ROWS * C_DIM];    // attention partial 0 -> merged y
__device__ __half g_y2 [M_ROWS * C_DIM];    // attention partial 1
__device__ float  g_x2 [M_ROWS * C_DIM];
__device__ __half g_h  [M_ROWS * FC_DIM];
// transposed (K-major, fp16, k-permuted) weights
__device__ __half g_wattnT[QKV_LD * C_DIM];
__device__ __half g_wprojT[C_DIM * C_DIM];
__device__ __half g_wfcT  [FC_DIM * C_DIM];
__device__ __half g_wmlpT [C_DIM * FC_DIM];

// ======================= helpers ==============================================
__device__ __forceinline__ uint32_t smem_u32(const void* p) {
    uint32_t a;
    asm("{ .reg .u64 t; cvta.to.shared.u64 t, %1; cvt.u32.u64 %0, t; }" : "=r"(a) : "l"(p));
    return a;
}
__device__ __forceinline__ void cp_async16(uint32_t s, const void* g) {
    asm volatile("cp.async.cg.shared.global [%0], [%1], 16;" :: "r"(s), "l"(g));
}
#define CP_COMMIT() asm volatile("cp.async.commit_group;" ::: "memory")
#define CP_WAIT(n)  asm volatile("cp.async.wait_group %0;" :: "n"(n) : "memory")

__device__ __forceinline__ float exp2a(float x) {
    float r;
    asm("ex2.approx.ftz.f32 %0, %1;" : "=f"(r) : "f"(x));
    return r;
}
// permute k within 16-groups: a thread's mma fragment halves
// {2t4, 2t4+1, 2t4+8, 2t4+9} become 4 contiguous halves at 16g + 4*t4.
__device__ __forceinline__ int perm16(int k) {
    int lo = k & 15;
    int p = ((lo & 7) >> 1) * 4 + ((lo >> 3) << 1) + (lo & 1);
    return (k & ~15) | p;
}
// smem half-index for tile row r, half col k; 16B-unit XOR swizzle
__device__ __forceinline__ int haddr(int r, int k) {
    int u = k >> 3;
    return r * 64 + (((u ^ (r & 7)) << 3) | (k & 7));
}
// D(16x8,f32) += A(16x16,f16) * B(16x8,f16)
__device__ __forceinline__ void mma_f16(float* d, const uint32_t* a, const uint32_t* b) {
    asm volatile(
        "mma.sync.aligned.m16n8k16.row.col.f32.f16.f16.f32 "
        "{%0,%1,%2,%3}, {%4,%5,%6,%7}, {%8,%9}, {%0,%1,%2,%3};"
        : "+f"(d[0]), "+f"(d[1]), "+f"(d[2]), "+f"(d[3])
        : "r"(a[0]), "r"(a[1]), "r"(a[2]), "r"(a[3]), "r"(b[0]), "r"(b[1]));
}
#define LDMX4(r, addr) \
    asm volatile("ldmatrix.sync.aligned.m8n8.x4.shared.b16 {%0,%1,%2,%3}, [%4];" \
        : "=r"((r)[0]), "=r"((r)[1]), "=r"((r)[2]), "=r"((r)[3]) : "r"(addr))
#define LDMX4T(r, addr) \
    asm volatile("ldmatrix.sync.aligned.m8n8.x4.trans.shared.b16 {%0,%1,%2,%3}, [%4];" \
        : "=r"((r)[0]), "=r"((r)[1]), "=r"((r)[2]), "=r"((r)[3]) : "r"(addr))

// ---------------- LayerNorm, warp-per-row (output: fp16, k-permuted) ----------
__global__ __launch_bounds__(256) void ln_kernel(const float* __restrict__ x,
                                                 const float* __restrict__ w,
                                                 __half* __restrict__ out) {
    int row = blockIdx.x * 8 + (threadIdx.x >> 5);
    int lane = threadIdx.x & 31;
    const float* xr = x + (size_t)row * C_DIM;
    float4 v[6];
    float s = 0.f, s2 = 0.f;
    #pragma unroll
    for (int j = 0; j < 6; j++) {
        v[j] = *(const float4*)(xr + j * 128 + lane * 4);
        s  += v[j].x + v[j].y + v[j].z + v[j].w;
        s2 += v[j].x * v[j].x + v[j].y * v[j].y + v[j].z * v[j].z + v[j].w * v[j].w;
    }
    #pragma unroll
    for (int o = 16; o; o >>= 1) {
        s  += __shfl_xor_sync(0xFFFFFFFFu, s,  o);
        s2 += __shfl_xor_sync(0xFFFFFFFFu, s2, o);
    }
    float mean = s * (1.f / C_DIM);
    float var  = s2 * (1.f / C_DIM) - mean * mean;
    float inv  = rsqrtf(var + 1e-5f);
    __half* orow = out + (size_t)row * C_DIM;
    #pragma unroll
    for (int j = 0; j < 6; j++) {
        int c = j * 128 + lane * 4;
        const float* f = &v[j].x;
        #pragma unroll
        for (int q = 0; q < 4; q++)
            orow[perm16(c + q)] = __float2half((f[q] - mean) * inv * w[c + q]);
    }
}

// ---------------- All 4 weight transposes in one launch ------------------------
#define SEG0 1728
#define SEG1 (SEG0 + 576)
#define SEG2 (SEG1 + 2304)
#define SEG3 (SEG2 + 2304)    // 6912 total

__global__ __launch_bounds__(256) void transpose_all_kernel(
    const float* __restrict__ in0, __half* __restrict__ out0,
    const float* __restrict__ in1, __half* __restrict__ out1,
    const float* __restrict__ in2, __half* __restrict__ out2,
    const float* __restrict__ in3, __half* __restrict__ out3)
{
    int bid = blockIdx.x;
    const float* in; __half* out; int rows, cols, t0, ntx;
    if (bid < SEG0)      { in = in0; out = out0; rows = C_DIM;  cols = QKV_LD; t0 = 0;    ntx = QKV_LD / 32; }
    else if (bid < SEG1) { in = in1; out = out1; rows = C_DIM;  cols = C_DIM;  t0 = SEG0; ntx = C_DIM / 32; }
    else if (bid < SEG2) { in = in2; out = out2; rows = C_DIM;  cols = FC_DIM; t0 = SEG1; ntx = FC_DIM / 32; }
    else                 { in = in3; out = out3; rows = FC_DIM; cols = C_DIM;  t0 = SEG2; ntx = C_DIM / 32; }
    int t = bid - t0;
    int bx = (t % ntx) * 32;
    int by = (t / ntx) * 32;

    __shared__ float tile[32][33];
    int tx = threadIdx.x & 31, ty = threadIdx.x >> 5;
    int x = bx + tx;
    #pragma unroll
    for (int j = 0; j < 32; j += 8)
        tile[ty + j][tx] = in[(size_t)(by + ty + j) * cols + x];
    __syncthreads();
    int ox = by + tx;
    #pragma unroll
    for (int j = 0; j < 32; j += 8) {
        float v = tile[tx][ty + j];
        out[(size_t)(bx + ty + j) * rows + perm16(ox)] = __float2half(v);
    }
}

// ---------------- fp16 mma GEMM, 128x256 CTA tile, warp tile 64x64 ------------
// MODE 0: C = A@B -> fp16 natural ; MODE 1: C = A@B + R -> f32 ;
// MODE 2: C = gelu(A@B) -> fp16, k-permuted
#define STAGE_H 24576                        // (128 + 256) * 64 halves
#define GEMM_SMEM_BYTES (3 * STAGE_H * 2)    // 147456

template<int MODE>
__global__ __launch_bounds__(256, 1) void mma_gemm_kernel(
    const __half* __restrict__ A, const __half* __restrict__ BT,
    const float* __restrict__ R, void* __restrict__ Cv,
    int M, int N, int K)
{
    extern __shared__ __half smh[];
    uint32_t sm_u = smem_u32(smh);

    int tid  = threadIdx.x;
    int wid  = tid >> 5, lane = tid & 31;
    int wm   = wid & 1;
    int wn   = wid >> 1;
    int g    = lane >> 2, t4 = lane & 3;
    int m0 = blockIdx.y * 128, n0 = blockIdx.x * 256;

    float acc[4][8][4];
    #pragma unroll
    for (int i = 0; i < 4; i++)
        #pragma unroll
        for (int j = 0; j < 8; j++)
            #pragma unroll
            for (int q = 0; q < 4; q++) acc[i][j][q] = 0.f;

    const int nch = K >> 6;

    auto issue = [&](int k0, int s) {
        uint32_t sb = sm_u + (uint32_t)(s * STAGE_H) * 2;
        #pragma unroll
        for (int t = 0; t < 4; t++) {
            int idx = t * 256 + tid;
            int row = idx >> 3, u = idx & 7;
            cp_async16(sb + (uint32_t)(row * 64 + ((u ^ (row & 7)) << 3)) * 2,
                       A + (size_t)(m0 + row) * K + k0 + u * 8);
        }
        uint32_t bb = sb + 8192u * 2;
        #pragma unroll
        for (int t = 0; t < 8; t++) {
            int idx = t * 256 + tid;
            int row = idx >> 3, u = idx & 7;
            cp_async16(bb + (uint32_t)(row * 64 + ((u ^ (row & 7)) << 3)) * 2,
                       BT + (size_t)(n0 + row) * K + k0 + u * 8);
        }
    };

    issue(0, 0); CP_COMMIT();
    if (nch > 1) { issue(64, 1); CP_COMMIT(); }

    for (int ic = 0; ic < nch; ic++) {
        if (ic + 1 < nch) CP_WAIT(1);
        else              CP_WAIT(0);
        __syncthreads();
        if (ic + 2 < nch) { issue((ic + 2) * 64, (ic + 2) % 3); CP_COMMIT(); }

        const __half* Ah = smh + (ic % 3) * STAGE_H;
        const __half* Bh = Ah + 8192;
        #pragma unroll
        for (int ks = 0; ks < 4; ks++) {
            uint32_t a[4][4], b[8][2];
            int kc = ks * 16 + 4 * t4;
            #pragma unroll
            for (int mt = 0; mt < 4; mt++) {
                int r = wm * 64 + mt * 16 + g;
                uint2 lo = *(const uint2*)(Ah + haddr(r,     kc));
                uint2 hi = *(const uint2*)(Ah + haddr(r + 8, kc));
                a[mt][0] = lo.x; a[mt][2] = lo.y;
                a[mt][1] = hi.x; a[mt][3] = hi.y;
            }
            #pragma unroll
            for (int nt = 0; nt < 8; nt++) {
                int nr = wn * 64 + nt * 8 + g;
                uint2 bv = *(const uint2*)(Bh + haddr(nr, kc));
                b[nt][0] = bv.x; b[nt][1] = bv.y;
            }
            #pragma unroll
            for (int mt = 0; mt < 4; mt++)
                #pragma unroll
                for (int nt = 0; nt < 8; nt++)
                    mma_f16(acc[mt][nt], a[mt], b[nt]);
        }
    }

    #pragma unroll
    for (int mt = 0; mt < 4; mt++) {
        int r0 = m0 + wm * 64 + mt * 16 + g;
        #pragma unroll
        for (int nt = 0; nt < 8; nt++) {
            int c = n0 + wn * 64 + nt * 8 + 2 * t4;
            #pragma unroll
            for (int half_ = 0; half_ < 2; half_++) {
                int r = r0 + half_ * 8;
                float v0 = acc[mt][nt][half_ * 2 + 0];
                float v1 = acc[mt][nt][half_ * 2 + 1];
                if (MODE == 1) {
                    float* C = (float*)Cv;
                    float2 rv = *(const float2*)(R + (size_t)r * N + c);
                    v0 += rv.x; v1 += rv.y;
                    *(float2*)(C + (size_t)r * N + c) = make_float2(v0, v1);
                } else if (MODE == 2) {
                    __half* C = (__half*)Cv;
                    v0 = 0.5f * v0 * (1.0f + erff(v0 * 0.70710678118654752f));
                    v1 = 0.5f * v1 * (1.0f + erff(v1 * 0.70710678118654752f));
                    C[(size_t)r * N + perm16(c)]     = __float2half(v0);
                    C[(size_t)r * N + perm16(c + 1)] = __float2half(v1);
                } else {
                    __half* C = (__half*)Cv;
                    *(__half2*)(C + (size_t)r * N + c) = __floats2half2_rn(v0, v1);
                }
            }
        }
    }
}

// ---------------- Attention: fp16 mma, 128q blocks, split-K (2 CTAs/block) ----
// scores = exp(s*(q2+k2-2qk)), s=-1/16; exp(s*k2) folded into V per tile so the
// per-element path is 1 FMA + 1 ex2.approx. Causal, unnormalized, split-K sums.
#define ATTN_SMEM_BYTES (24576 * 2 + 128 * 4)

__global__ __launch_bounds__(256, 2) void attn_kernel(const __half* __restrict__ qkv,
                                                      __half* __restrict__ y0,
                                                      __half* __restrict__ y1) {
    int qi = gridDim.x - 1 - blockIdx.x;   // big blocks first
    int h = blockIdx.y;
    int b = blockIdx.z & 1;
    int sp = blockIdx.z >> 1;              // split index 0/1
    int kt0 = sp * (qi + 1);
    int kt1 = kt0 + qi + 1;
    __half* yb = sp ? y1 : y0;

    extern __shared__ __half smh[];
    __half* Qs = smh;                 // 128 x 64
    __half* Ks = smh + 8192;          // 2 x 64 x 64
    __half* Vs = smh + 16384;         // 2 x 64 x 64
    float* q2s = (float*)(smh + 24576);   // 128
    uint32_t Qu = smem_u32(Qs), Ku = smem_u32(Ks), Vu = smem_u32(Vs);

    int tid = threadIdx.x, wid = tid >> 5, lane = tid & 31;
    int g = lane >> 2, t4 = lane & 3;
    int qrow0 = wid * 16;
    const float scale = -0.0625f;              // -1/(2*sqrt(64))
    const float L2E   = 1.44269504f;
    const float C2L   = 0.125f * L2E;          // (-2*scale)*log2e

    // load Q (128 rows x 8 units)
    {
        const __half* qg = qkv + ((size_t)(b * T_SEQ + qi * 128)) * QKV_LD + h * 64;
        #pragma unroll
        for (int t = 0; t < 4; t++) {
            int idx = t * 256 + tid;
            int r = idx >> 3, u = idx & 7;
            cp_async16(Qu + (uint32_t)(r * 64 + ((u ^ (r & 7)) << 3)) * 2,
                       qg + (size_t)r * QKV_LD + u * 8);
        }
    }
    auto loadKV = [&](int kt, int bb) {
        const __half* kg = qkv + ((size_t)(b * T_SEQ + kt * 64)) * QKV_LD + C_DIM + h * 64;
        const __half* vg = kg + C_DIM;
        uint32_t kb = Ku + (uint32_t)(bb * 4096) * 2;
        uint32_t vb = Vu + (uint32_t)(bb * 4096) * 2;
        #pragma unroll
        for (int t = 0; t < 2; t++) {
            int idx = t * 256 + tid;
            int r = idx >> 3, u = idx & 7;
            uint32_t so = (uint32_t)(r * 64 + ((u ^ (r & 7)) << 3)) * 2;
            cp_async16(kb + so, kg + (size_t)r * QKV_LD + u * 8);
            cp_async16(vb + so, vg + (size_t)r * QKV_LD + u * 8);
        }
    };
    loadKV(kt0, 0); CP_COMMIT();

    uint32_t qf[4][4];
    float oacc[8][4];
    #pragma unroll
    for (int i = 0; i < 8; i++)
        #pragma unroll
        for (int q = 0; q < 4; q++) oacc[i][q] = 0.f;

    int qg0 = qi * 128 + qrow0 + g;
    int qg1 = qg0 + 8;
    float ra2a = 0.f, ra2b = 0.f;   // scale*q2*log2e per row

    for (int kt = kt0; kt < kt1; kt++) {
        int buf = (kt - kt0) & 1;
        if (kt + 1 < kt1) { loadKV(kt + 1, buf ^ 1); CP_COMMIT(); CP_WAIT(1); }
        else              { CP_WAIT(0); }
        __syncthreads();

        if (kt == kt0 && tid < 128) {      // q2 (once per CTA)
            int r = tid;
            float s = 0.f;
            #pragma unroll
            for (int u = 0; u < 8; u++) {
                uint4 v = *(const uint4*)(Qs + r * 64 + ((u ^ (r & 7)) << 3));
                const uint32_t* w = &v.x;
                #pragma unroll
                for (int j = 0; j < 4; j++) {
                    float2 f = __half22float2(*(const __half2*)&w[j]);
                    s += f.x * f.x + f.y * f.y;
                }
            }
            q2s[r] = s;
        }

        // ---- quad pass: k2 per key row, fold exp(scale*k2) into V ----
        {
            int r = tid >> 2;              // key row 0..63
            int seg = tid & 3;             // 16-half segment
            const __half* kb = Ks + buf * 4096;
            __half* vb = Vs + buf * 4096;
            uint4 kv0 = *(const uint4*)(kb + r * 64 + seg * 16);
            uint4 kv1 = *(const uint4*)(kb + r * 64 + seg * 16 + 8);
            float s = 0.f;
            const uint32_t* w0 = &kv0.x;
            const uint32_t* w1 = &kv1.x;
            #pragma unroll
            for (int j = 0; j < 4; j++) {
                float2 f0 = __half22float2(*(const __half2*)&w0[j]);
                float2 f1 = __half22float2(*(const __half2*)&w1[j]);
                s += f0.x * f0.x + f0.y * f0.y + f1.x * f1.x + f1.y * f1.y;
            }
            s += __shfl_xor_sync(0xFFFFFFFFu, s, 1);
            s += __shfl_xor_sync(0xFFFFFFFFu, s, 2);
            float ek = exp2a(scale * L2E * s);
            __half2 ekh = __float2half2_rn(ek);
            uint4 vv0 = *(const uint4*)(vb + r * 64 + seg * 16);
            uint4 vv1 = *(const uint4*)(vb + r * 64 + seg * 16 + 8);
            __half2* h0 = (__half2*)&vv0;
            __half2* h1 = (__half2*)&vv1;
            #pragma unroll
            for (int j = 0; j < 4; j++) { h0[j] = __hmul2(h0[j], ekh); h1[j] = __hmul2(h1[j], ekh); }
            *(uint4*)(vb + r * 64 + seg * 16)     = vv0;
            *(uint4*)(vb + r * 64 + seg * 16 + 8) = vv1;
        }
        __syncthreads();

        if (kt == kt0) {
            #pragma unroll
            for (int ks = 0; ks < 4; ks++) {
                int m = lane >> 3;
                int r = qrow0 + ((m & 1) << 3) + (lane & 7);
                int d0 = ks * 16 + ((m >> 1) << 3);
                LDMX4(qf[ks], Qu + (uint32_t)haddr(r, d0) * 2);
            }
            ra2a = scale * L2E * q2s[qrow0 + g];
            ra2b = scale * L2E * q2s[qrow0 + g + 8];
        }

        uint32_t kbase = Ku + (uint32_t)(buf * 4096) * 2;
        uint32_t vbase = Vu + (uint32_t)(buf * 4096) * 2;

        // ---- S = Q @ K^T ----
        float sacc[8][4];
        #pragma unroll
        for (int i = 0; i < 8; i++)
            #pragma unroll
            for (int q = 0; q < 4; q++) sacc[i][q] = 0.f;
        #pragma unroll
        for (int ks = 0; ks < 4; ks++) {
            uint32_t kf[4][4];
            #pragma unroll
            for (int nt2 = 0; nt2 < 4; nt2++) {
                int m = lane >> 3;
                int tok = nt2 * 16 + ((m >> 1) << 3) + (lane & 7);
                int d0 = ks * 16 + ((m & 1) << 3);
                LDMX4(kf[nt2], kbase + (uint32_t)haddr(tok, d0) * 2);
            }
            #pragma unroll
            for (int nt2 = 0; nt2 < 4; nt2++) {
                mma_f16(sacc[2 * nt2],     qf[ks], &kf[nt2][0]);
                mma_f16(sacc[2 * nt2 + 1], qf[ks], &kf[nt2][2]);
            }
        }

        // ---- P' = exp2(fma(qk, C2L, ra2)), causal mask, fp16 in registers ----
        uint32_t ph[8], ph2[8];
        int kc0 = kt * 64 + 2 * t4;
        #pragma unroll
        for (int nt = 0; nt < 8; nt++) {
            int c0 = kc0 + nt * 8;
            float e00 = (c0     <= qg0) ? exp2a(fmaf(sacc[nt][0], C2L, ra2a)) : 0.f;
            float e01 = (c0 + 1 <= qg0) ? exp2a(fmaf(sacc[nt][1], C2L, ra2a)) : 0.f;
            float e10 = (c0     <= qg1) ? exp2a(fmaf(sacc[nt][2], C2L, ra2b)) : 0.f;
            float e11 = (c0 + 1 <= qg1) ? exp2a(fmaf(sacc[nt][3], C2L, ra2b)) : 0.f;
            __half2 p0 = __floats2half2_rn(e00, e01);
            __half2 p1 = __floats2half2_rn(e10, e11);
            ph[nt]  = *(uint32_t*)&p0;
            ph2[nt] = *(uint32_t*)&p1;
        }

        // ---- O += P' @ V' ----
        #pragma unroll
        for (int kc = 0; kc < 4; kc++) {
            uint32_t vf[4][4];
            #pragma unroll
            for (int dn2 = 0; dn2 < 4; dn2++) {
                int m = lane >> 3;
                int tok = kc * 16 + ((m & 1) << 3) + (lane & 7);
                int d0 = dn2 * 16 + ((m >> 1) << 3);
                LDMX4T(vf[dn2], vbase + (uint32_t)haddr(tok, d0) * 2);
            }
            uint32_t a[4] = { ph[2 * kc], ph2[2 * kc], ph[2 * kc + 1], ph2[2 * kc + 1] };
            #pragma unroll
            for (int dn2 = 0; dn2 < 4; dn2++) {
                mma_f16(oacc[2 * dn2],     a, &vf[dn2][0]);
                mma_f16(oacc[2 * dn2 + 1], a, &vf[dn2][2]);
            }
        }
        __syncthreads();
    }

    // ---- write partial y (fp16, perm16) ----
    size_t row0 = (size_t)(b * T_SEQ + qi * 128 + qrow0 + g);
    #pragma unroll
    for (int dn = 0; dn < 8; dn++) {
        int col = h * 64 + dn * 8 + 2 * t4;
        int pc = perm16(col);
        __half2 v0 = __floats2half2_rn(oacc[dn][0], oacc[dn][1]);
        __half2 v1 = __floats2half2_rn(oacc[dn][2], oacc[dn][3]);
        *(__half2*)(yb + row0 * C_DIM + pc)       = v0;
        *(__half2*)(yb + (row0 + 8) * C_DIM + pc) = v1;
    }
}

// ---------------- merge split-K partials: y = y0 + y1 (in place on y0) --------
__global__ __launch_bounds__(256) void merge_y_kernel(__half2* __restrict__ y0,
                                                      const __half2* __restrict__ y1) {
    const int n2 = M_ROWS * C_DIM / 2;
    int i = blockIdx.x * 256 + threadIdx.x;
    int stride = gridDim.x * 256;
    for (; i < n2; i += stride)
        y0[i] = __hadd2(y0[i], y1[i]);
}

// ---------------- launch ------------------------------------------------------
extern "C" void kernel_launch(void* const* d_in, const int* in_sizes, int n_in,
                              void* d_out, int out_size) {
    const float* x           = (const float*)d_in[0];
    const float* w_ln1       = (const float*)d_in[1];
    const float* w_attn      = (const float*)d_in[2];
    const float* w_attn_proj = (const float*)d_in[3];
    const float* w_ln2       = (const float*)d_in[4];
    const float* w_fc        = (const float*)d_in[5];
    const float* w_mlp_proj  = (const float*)d_in[6];
    float* out = (float*)d_out;

    __half *xn, *qkv, *y, *y2, *hbuf, *wattnT, *wprojT, *wfcT, *wmlpT;
    float *x2;
    cudaGetSymbolAddress((void**)&xn,     g_xn);
    cudaGetSymbolAddress((void**)&qkv,    g_qkv);
    cudaGetSymbolAddress((void**)&y,      g_y);
    cudaGetSymbolAddress((void**)&y2,     g_y2);
    cudaGetSymbolAddress((void**)&x2,     g_x2);
    cudaGetSymbolAddress((void**)&hbuf,   g_h);
    cudaGetSymbolAddress((void**)&wattnT, g_wattnT);
    cudaGetSymbolAddress((void**)&wprojT, g_wprojT);
    cudaGetSymbolAddress((void**)&wfcT,   g_wfcT);
    cudaGetSymbolAddress((void**)&wmlpT,  g_wmlpT);

    cudaFuncSetAttribute(attn_kernel, cudaFuncAttributeMaxDynamicSharedMemorySize, ATTN_SMEM_BYTES);
    cudaFuncSetAttribute(mma_gemm_kernel<0>, cudaFuncAttributeMaxDynamicSharedMemorySize, GEMM_SMEM_BYTES);
    cudaFuncSetAttribute(mma_gemm_kernel<1>, cudaFuncAttributeMaxDynamicSharedMemorySize, GEMM_SMEM_BYTES);
    cudaFuncSetAttribute(mma_gemm_kernel<2>, cudaFuncAttributeMaxDynamicSharedMemorySize, GEMM_SMEM_BYTES);

    // 0. all weight transposes, one launch
    transpose_all_kernel<<<SEG3, 256>>>(w_attn, wattnT, w_attn_proj, wprojT,
                                        w_fc, wfcT, w_mlp_proj, wmlpT);
    // 1. ln1(x) -> xn  (fp16, k-permuted)
    ln_kernel<<<M_ROWS / 8, 256>>>(x, w_ln1, xn);
    // 2. qkv = xn @ w_attn  (fp16 natural out)
    mma_gemm_kernel<0><<<dim3(QKV_LD / 256, M_ROWS / 128), 256, GEMM_SMEM_BYTES>>>(
        xn, wattnT, nullptr, qkv, M_ROWS, QKV_LD, C_DIM);
    // 3. attention, 2-way split-K -> y (partial 0), y2 (partial 1)
    attn_kernel<<<dim3(T_SEQ / 128, H_HEADS, 4), 256, ATTN_SMEM_BYTES>>>(qkv, y, y2);
    // 3b. y += y2
    merge_y_kernel<<<1184, 256>>>((__half2*)y, (const __half2*)y2);
    // 4. x2 = y @ w_attn_proj + x  (f32 out)
    mma_gemm_kernel<1><<<dim3(C_DIM / 256, M_ROWS / 128), 256, GEMM_SMEM_BYTES>>>(
        y, wprojT, x, x2, M_ROWS, C_DIM, C_DIM);
    // 5. ln2(x2) -> xn
    ln_kernel<<<M_ROWS / 8, 256>>>(x2, w_ln2, xn);
    // 6. h = gelu(xn @ w_fc)  (fp16, k-permuted)
    mma_gemm_kernel<2><<<dim3(FC_DIM / 256, M_ROWS / 128), 256, GEMM_SMEM_BYTES>>>(
        xn, wfcT, nullptr, hbuf, M_ROWS, FC_DIM, C_DIM);
    // 7. out = h @ w_mlp_proj + x2  (f32 out)
    mma_gemm_kernel<1><<<dim3(C_DIM / 256, M_ROWS / 128), 256, GEMM_SMEM_BYTES>>>(
        hbuf, wmlpT, x2, out, M_ROWS, C_DIM, FC_DIM);
}